// round 2
// baseline (speedup 1.0000x reference)
#include <cuda_runtime.h>
#include <math.h>

#define BB 2
#define LL 2048
#define DM 1024
#define NH 16
#define HD 64
#define DFF 4096
#define NTOK (BB*LL)
#define LN_EPS 1e-5f

// ---------------- scratch (no allocation allowed) ----------------
__device__ float g_xn [NTOK*DM];
__device__ float g_q  [NTOK*DM];
__device__ float g_k  [NTOK*DM];
__device__ float g_v  [NTOK*DM];
__device__ float g_o  [NTOK*DM];
__device__ float g_x2 [NTOK*DM];
__device__ float g_xn2[NTOK*DM];
__device__ float g_h  [NTOK*DFF];

// ---------------- f32x2 + cp.async helpers ----------------
__device__ __forceinline__ unsigned long long pack2(float x, float y) {
    unsigned long long r;
    asm("mov.b64 %0, {%1, %2};" : "=l"(r) : "f"(x), "f"(y));
    return r;
}
__device__ __forceinline__ void unpack2(unsigned long long v, float& x, float& y) {
    asm("mov.b64 {%0, %1}, %2;" : "=f"(x), "=f"(y) : "l"(v));
}
__device__ __forceinline__ unsigned long long fma2(unsigned long long a, unsigned long long b,
                                                   unsigned long long c) {
    unsigned long long d;
    asm("fma.rn.f32x2 %0, %1, %2, %3;" : "=l"(d) : "l"(a), "l"(b), "l"(c));
    return d;
}
__device__ __forceinline__ unsigned long long mul2(unsigned long long a, unsigned long long b) {
    unsigned long long d;
    asm("mul.rn.f32x2 %0, %1, %2;" : "=l"(d) : "l"(a), "l"(b));
    return d;
}
__device__ __forceinline__ void cp16(void* smem, const void* g) {
    unsigned sa = (unsigned)__cvta_generic_to_shared(smem);
    asm volatile("cp.async.cg.shared.global [%0], [%1], 16;" :: "r"(sa), "l"(g));
}
#define CP_COMMIT() asm volatile("cp.async.commit_group;" ::: "memory")
#define CP_WAIT0()  asm volatile("cp.async.wait_group 0;" ::: "memory")

// ---------------- LayerNorm ----------------
__global__ void ln_kernel(const float* __restrict__ x, const float* __restrict__ g,
                          const float* __restrict__ b, float* __restrict__ y)
{
    int row = blockIdx.x;
    int t = threadIdx.x;
    const float4* xr = (const float4*)(x + (size_t)row * DM);
    float4 v = xr[t];
    float s  = v.x + v.y + v.z + v.w;
    float ss = v.x*v.x + v.y*v.y + v.z*v.z + v.w*v.w;
#pragma unroll
    for (int o = 16; o; o >>= 1) {
        s  += __shfl_xor_sync(0xffffffffu, s,  o);
        ss += __shfl_xor_sync(0xffffffffu, ss, o);
    }
    __shared__ float sh_s[8], sh_ss[8];
    int w = t >> 5, lane = t & 31;
    if (lane == 0) { sh_s[w] = s; sh_ss[w] = ss; }
    __syncthreads();
    if (t < 32) {
        s  = (t < 8) ? sh_s[t]  : 0.f;
        ss = (t < 8) ? sh_ss[t] : 0.f;
#pragma unroll
        for (int o = 4; o; o >>= 1) {
            s  += __shfl_xor_sync(0xffffffffu, s,  o);
            ss += __shfl_xor_sync(0xffffffffu, ss, o);
        }
        if (t == 0) { sh_s[0] = s; sh_ss[0] = ss; }
    }
    __syncthreads();
    float mu  = sh_s[0] * (1.f / DM);
    float var = sh_ss[0] * (1.f / DM) - mu * mu;
    float inv = rsqrtf(var + LN_EPS);
    float4 gv = ((const float4*)g)[t];
    float4 bv = ((const float4*)b)[t];
    float4 o4;
    o4.x = (v.x - mu) * inv * gv.x + bv.x;
    o4.y = (v.y - mu) * inv * gv.y + bv.y;
    o4.z = (v.z - mu) * inv * gv.z + bv.z;
    o4.w = (v.w - mu) * inv * gv.w + bv.w;
    ((float4*)(y + (size_t)row * DM))[t] = o4;
}

// ---------------- SGEMM v2: f32x2 + cp.async double-buffer ----------------
// 128x128 tile, BK=16, 256 threads, 8x8 microtile (as 8x4 f32x2 pairs).
// As layout: [row(128)][k(16)], Bs layout: [k(16)][n(128)].
template<bool RELU, bool RES>
__global__ __launch_bounds__(256, 2)
void sgemm_kernel(const float* __restrict__ A, const float* __restrict__ Bm,
                  const float* __restrict__ bias, const float* __restrict__ res,
                  float* __restrict__ C, int M, int N, int K)
{
    __shared__ float As[2][128*16];
    __shared__ float Bs[2][16*128];
    int t  = threadIdx.x;
    int m0 = blockIdx.y * 128;
    int n0 = blockIdx.x * 128;
    int ty = t >> 4, tx = t & 15;

    unsigned long long acc2[8][4];
#pragma unroll
    for (int i = 0; i < 8; i++)
#pragma unroll
        for (int j = 0; j < 4; j++) acc2[i][j] = 0ull;

    // prologue: async-load k-slab 0
#pragma unroll
    for (int u = 0; u < 2; u++) {
        int idx = t + u * 256;
        int ar = idx >> 2, ak = idx & 3;
        cp16(&As[0][ar*16 + ak*4], A + (size_t)(m0 + ar) * K + ak * 4);
        int br = idx >> 5, bc = idx & 31;
        cp16(&Bs[0][br*128 + bc*4], Bm + (size_t)br * N + n0 + bc * 4);
    }
    CP_COMMIT(); CP_WAIT0(); __syncthreads();

    int NK = K >> 4;
    for (int k0 = 0; k0 < NK; k0++) {
        int cur = k0 & 1;
        if (k0 + 1 < NK) {
            int nxt = cur ^ 1;
            int kb = (k0 + 1) << 4;
#pragma unroll
            for (int u = 0; u < 2; u++) {
                int idx = t + u * 256;
                int ar = idx >> 2, ak = idx & 3;
                cp16(&As[nxt][ar*16 + ak*4], A + (size_t)(m0 + ar) * K + kb + ak * 4);
                int br = idx >> 5, bc = idx & 31;
                cp16(&Bs[nxt][br*128 + bc*4], Bm + (size_t)(kb + br) * N + n0 + bc * 4);
            }
        }
        CP_COMMIT();

        const float* as = &As[cur][0];
        const float* bs = &Bs[cur][0];
#pragma unroll
        for (int k2 = 0; k2 < 8; k2++) {
            float2 a2f[8];
#pragma unroll
            for (int i = 0; i < 8; i++)
                a2f[i] = *(const float2*)(as + (ty*8 + i) * 16 + k2 * 2);
#pragma unroll
            for (int kk = 0; kk < 2; kk++) {
                const float* brow = bs + (k2*2 + kk) * 128 + tx * 8;
                ulonglong2 b01 = *(const ulonglong2*)(brow);
                ulonglong2 b23 = *(const ulonglong2*)(brow + 4);
#pragma unroll
                for (int i = 0; i < 8; i++) {
                    float av = kk ? a2f[i].y : a2f[i].x;
                    unsigned long long a2 = pack2(av, av);
                    acc2[i][0] = fma2(a2, b01.x, acc2[i][0]);
                    acc2[i][1] = fma2(a2, b01.y, acc2[i][1]);
                    acc2[i][2] = fma2(a2, b23.x, acc2[i][2]);
                    acc2[i][3] = fma2(a2, b23.y, acc2[i][3]);
                }
            }
        }
        CP_WAIT0(); __syncthreads();
    }

    float bj[8];
#pragma unroll
    for (int j = 0; j < 8; j++) bj[j] = bias[n0 + tx*8 + j];

#pragma unroll
    for (int i = 0; i < 8; i++) {
        size_t crow = (size_t)(m0 + ty*8 + i) * N + n0 + tx*8;
        float val[8];
#pragma unroll
        for (int j4 = 0; j4 < 4; j4++)
            unpack2(acc2[i][j4], val[j4*2], val[j4*2+1]);
#pragma unroll
        for (int j = 0; j < 8; j++) {
            float vv = val[j] + bj[j];
            if (RES)  vv += res[crow + j];
            if (RELU) vv = fmaxf(vv, 0.f);
            val[j] = vv;
        }
        *(float4*)(C + crow)     = make_float4(val[0], val[1], val[2], val[3]);
        *(float4*)(C + crow + 4) = make_float4(val[4], val[5], val[6], val[7]);
    }
}

// ---------------- RoPE (heads < 8) + q scale (all heads) ----------------
__global__ void rope_kernel(float* __restrict__ q, float* __restrict__ k)
{
    int idx = blockIdx.x * blockDim.x + threadIdx.x;
    const int total = NTOK * NH * (HD / 2);
    if (idx >= total) return;
    int i   = idx & 31;
    int h   = (idx >> 5) & 15;
    int tok = idx >> 9;
    int l   = tok & (LL - 1);
    size_t base = (size_t)tok * DM + h * HD + 2 * i;

    float q1 = q[base], q2 = q[base + 1];
    if (h < 8) {
        double invf = pow(10000.0, -(double)i / 32.0);
        float ang = (float)((double)l * invf);
        float cs = (float)cos((double)ang);
        float sn = (float)sin((double)ang);
        float qe = q1 * cs - q2 * sn;
        float qo = q1 * sn + q2 * cs;
        q1 = qe; q2 = qo;
        float k1 = k[base], k2 = k[base + 1];
        k[base]     = k1 * cs - k2 * sn;
        k[base + 1] = k1 * sn + k2 * cs;
    }
    q[base]     = q1 * 0.125f;
    q[base + 1] = q2 * 0.125f;
}

// ---------------- Flash attention v2 ----------------
// 32 q-rows per block, 256 threads: thread (r = t>>3, lane8 = t&7).
// S phase: quad = lane8>>1 owns 16 S-cols, e = lane8&1 owns a 32-dim half of q.
// PV phase: lane8 owns 8 output dims. Single __syncthreads per KV tile.
// K double-buffered, V triple-buffered, P double-buffered; cp.async overlap.
__global__ __launch_bounds__(256, 2)
void attn_kernel(const float* __restrict__ q, const float* __restrict__ k,
                 const float* __restrict__ v, float* __restrict__ o)
{
    extern __shared__ float sm[];
    // layout (floats): k[2][4096] | v[3][4096] | p[2][2048]
    float* KS = sm;             // + (j&1)*4096
    float* VS = sm + 8192;      // + (j%3)*4096
    float* PS = sm + 20480;     // + (j&1)*2048

    int qt = blockIdx.x;
    int h  = blockIdx.y;
    int b  = blockIdx.z;
    int t  = threadIdx.x;
    int r     = t >> 3;       // 0..31
    int lane8 = t & 7;
    int quad  = lane8 >> 1;   // 0..3: S column group
    int e     = lane8 & 1;    // 0..1: q dim half

    // q half in registers (32 floats = 16 packed pairs)
    size_t qbase = ((size_t)b * LL + qt * 32 + r) * DM + h * HD + e * 32;
    unsigned long long q2[16];
#pragma unroll
    for (int i = 0; i < 8; i++) {
        ulonglong2 u = *(const ulonglong2*)(q + qbase + i * 4);
        q2[2*i] = u.x; q2[2*i+1] = u.y;
    }

    unsigned long long acc2[4] = {0ull, 0ull, 0ull, 0ull};
    float m = -1e30f, lsum = 0.f;

    const float* kbh = k + (size_t)b * LL * DM + h * HD;
    const float* vbh = v + (size_t)b * LL * DM + h * HD;

    // preload tile 0
#pragma unroll
    for (int u = 0; u < 4; u++) {
        int idx = t + u * 256;
        int rr = idx >> 4, c4 = idx & 15;
        cp16(KS + rr*64 + c4*4, kbh + (size_t)rr * DM + c4 * 4);
        cp16(VS + rr*64 + c4*4, vbh + (size_t)rr * DM + c4 * 4);
    }
    CP_COMMIT(); CP_WAIT0(); __syncthreads();

    int vcur = 0;
    for (int j = 0; j < 32; j++) {
        // 1. issue async loads for tile j+1
        int vnxt = (vcur == 2) ? 0 : vcur + 1;
        if (j + 1 < 32) {
            const float* kn = kbh + (size_t)(j + 1) * 64 * DM;
            const float* vn = vbh + (size_t)(j + 1) * 64 * DM;
            float* kd = KS + ((j + 1) & 1) * 4096;
            float* vd = VS + vnxt * 4096;
#pragma unroll
            for (int u = 0; u < 4; u++) {
                int idx = t + u * 256;
                int rr = idx >> 4, c4 = idx & 15;
                cp16(kd + rr*64 + c4*4, kn + (size_t)rr * DM + c4 * 4);
                cp16(vd + rr*64 + c4*4, vn + (size_t)rr * DM + c4 * 4);
            }
        }
        CP_COMMIT();

        // 2. S_j: 16 columns, partial dot over this lane's 32 dims
        const float* ks = KS + (j & 1) * 4096;
        float s[16];
#pragma unroll
        for (int c16 = 0; c16 < 16; c16++) {
            const float* kr = ks + (quad * 16 + c16) * 64 + e * 32;
            unsigned long long sv = 0ull;
#pragma unroll
            for (int d = 0; d < 8; d++) {
                ulonglong2 kk = *(const ulonglong2*)(kr + d * 4);
                sv = fma2(q2[2*d],   kk.x, sv);
                sv = fma2(q2[2*d+1], kk.y, sv);
            }
            float lo, hi; unpack2(sv, lo, hi);
            float part = lo + hi;
            part += __shfl_xor_sync(0xffffffffu, part, 1);  // combine the two d-halves
            s[c16] = part;
        }

        // 3. PV_{j-1}
        if (j > 0) {
            int vp = (vcur == 0) ? 2 : vcur - 1;
            const float* vs = VS + vp * 4096;
            const float* ps = PS + ((j - 1) & 1) * 2048 + r * 64;
#pragma unroll 4
            for (int c4 = 0; c4 < 16; c4++) {
                float4 p4 = *(const float4*)(ps + c4 * 4);
                float pf[4] = {p4.x, p4.y, p4.z, p4.w};
#pragma unroll
                for (int cc = 0; cc < 4; cc++) {
                    unsigned long long pv2 = pack2(pf[cc], pf[cc]);
                    const float* vr = vs + (c4*4 + cc) * 64 + lane8 * 8;
                    ulonglong2 u0 = *(const ulonglong2*)(vr);
                    ulonglong2 u1 = *(const ulonglong2*)(vr + 4);
                    acc2[0] = fma2(pv2, u0.x, acc2[0]);
                    acc2[1] = fma2(pv2, u0.y, acc2[1]);
                    acc2[2] = fma2(pv2, u1.x, acc2[2]);
                    acc2[3] = fma2(pv2, u1.y, acc2[3]);
                }
            }
        }

        // 4. online softmax for tile j
        float mloc = s[0];
#pragma unroll
        for (int c16 = 1; c16 < 16; c16++) mloc = fmaxf(mloc, s[c16]);
        mloc = fmaxf(mloc, __shfl_xor_sync(0xffffffffu, mloc, 2));
        mloc = fmaxf(mloc, __shfl_xor_sync(0xffffffffu, mloc, 4));
        float mnew = fmaxf(m, mloc);
        float al = __expf(m - mnew);
        float psum = 0.f;
#pragma unroll
        for (int c16 = 0; c16 < 16; c16++) {
            float p = __expf(s[c16] - mnew);
            s[c16] = p;
            psum += p;
        }
        psum += __shfl_xor_sync(0xffffffffu, psum, 2);
        psum += __shfl_xor_sync(0xffffffffu, psum, 4);
        lsum = lsum * al + psum;
        m = mnew;
        unsigned long long al2 = pack2(al, al);
#pragma unroll
        for (int i = 0; i < 4; i++) acc2[i] = mul2(acc2[i], al2);

        // store P_j (each e-lane stores its 8 of the 16 shared values)
        {
            float* pd = PS + (j & 1) * 2048 + r * 64 + quad * 16 + e * 8;
            int base = e * 8;
            *(float4*)(pd)     = make_float4(s[base+0], s[base+1], s[base+2], s[base+3]);
            *(float4*)(pd + 4) = make_float4(s[base+4], s[base+5], s[base+6], s[base+7]);
        }

        CP_WAIT0();
        __syncthreads();
        vcur = vnxt;
    }

    // epilogue: PV for tile 31 (vcur now = 32%3=2, so prev = 1; p buffer = 31&1 = 1)
    {
        const float* vs = VS + 1 * 4096;
        const float* ps = PS + 1 * 2048 + r * 64;
#pragma unroll 4
        for (int c4 = 0; c4 < 16; c4++) {
            float4 p4 = *(const float4*)(ps + c4 * 4);
            float pf[4] = {p4.x, p4.y, p4.z, p4.w};
#pragma unroll
            for (int cc = 0; cc < 4; cc++) {
                unsigned long long pv2 = pack2(pf[cc], pf[cc]);
                const float* vr = vs + (c4*4 + cc) * 64 + lane8 * 8;
                ulonglong2 u0 = *(const ulonglong2*)(vr);
                ulonglong2 u1 = *(const ulonglong2*)(vr + 4);
                acc2[0] = fma2(pv2, u0.x, acc2[0]);
                acc2[1] = fma2(pv2, u0.y, acc2[1]);
                acc2[2] = fma2(pv2, u1.x, acc2[2]);
                acc2[3] = fma2(pv2, u1.y, acc2[3]);
            }
        }
    }

    float invl = 1.f / lsum;
    float ov[8];
#pragma unroll
    for (int i = 0; i < 4; i++) {
        unpack2(acc2[i], ov[2*i], ov[2*i+1]);
        ov[2*i]   *= invl;
        ov[2*i+1] *= invl;
    }
    size_t obase = ((size_t)b * LL + qt * 32 + r) * DM + h * HD + lane8 * 8;
    *(float4*)(o + obase)     = make_float4(ov[0], ov[1], ov[2], ov[3]);
    *(float4*)(o + obase + 4) = make_float4(ov[4], ov[5], ov[6], ov[7]);
}

// ---------------- launcher ----------------
extern "C" void kernel_launch(void* const* d_in, const int* in_sizes, int n_in,
                              void* d_out, int out_size)
{
    const float* x     = (const float*)d_in[0];
    const float* Wq    = (const float*)d_in[1];
    const float* bq    = (const float*)d_in[2];
    const float* Wk    = (const float*)d_in[3];
    const float* bk    = (const float*)d_in[4];
    const float* Wv    = (const float*)d_in[5];
    const float* bv    = (const float*)d_in[6];
    const float* Wo    = (const float*)d_in[7];
    const float* bo    = (const float*)d_in[8];
    const float* ln1_g = (const float*)d_in[9];
    const float* ln1_b = (const float*)d_in[10];
    const float* ln2_g = (const float*)d_in[11];
    const float* ln2_b = (const float*)d_in[12];
    const float* W1    = (const float*)d_in[13];
    const float* b1    = (const float*)d_in[14];
    const float* W2    = (const float*)d_in[15];
    const float* b2    = (const float*)d_in[16];
    float* out = (float*)d_out;

    float *xn, *q, *k, *v, *o, *x2, *xn2, *hb;
    cudaGetSymbolAddress((void**)&xn,  g_xn);
    cudaGetSymbolAddress((void**)&q,   g_q);
    cudaGetSymbolAddress((void**)&k,   g_k);
    cudaGetSymbolAddress((void**)&v,   g_v);
    cudaGetSymbolAddress((void**)&o,   g_o);
    cudaGetSymbolAddress((void**)&x2,  g_x2);
    cudaGetSymbolAddress((void**)&xn2, g_xn2);
    cudaGetSymbolAddress((void**)&hb,  g_h);

    static bool attr_set = false;
    if (!attr_set) {
        cudaFuncSetAttribute(attn_kernel, cudaFuncAttributeMaxDynamicSharedMemorySize, 98304);
        attr_set = true;
    }

    ln_kernel<<<NTOK, 256>>>(x, ln1_g, ln1_b, xn);

    dim3 g1(DM / 128, NTOK / 128);
    sgemm_kernel<false, false><<<g1, 256>>>(xn, Wq, bq, nullptr, q, NTOK, DM, DM);
    sgemm_kernel<false, false><<<g1, 256>>>(x,  Wk, bk, nullptr, k, NTOK, DM, DM);
    sgemm_kernel<false, false><<<g1, 256>>>(x,  Wv, bv, nullptr, v, NTOK, DM, DM);

    const int pairs = NTOK * NH * (HD / 2);
    rope_kernel<<<(pairs + 255) / 256, 256>>>(q, k);

    dim3 ga(LL / 32, NH, BB);   // (64, 16, 2)
    attn_kernel<<<ga, 256, 98304>>>(q, k, v, o);

    sgemm_kernel<false, true><<<g1, 256>>>(o, Wo, bo, x, x2, NTOK, DM, DM);

    ln_kernel<<<NTOK, 256>>>(x2, ln2_g, ln2_b, xn2);

    dim3 g2(DFF / 128, NTOK / 128);
    sgemm_kernel<true, false><<<g2, 256>>>(xn2, W1, b1, nullptr, hb, NTOK, DFF, DM);
    sgemm_kernel<false, true><<<g1, 256>>>(hb, W2, b2, x2, out, NTOK, DM, DFF);
}

// round 3
// speedup vs baseline: 7.9061x; 7.9061x over previous
#include <cuda_runtime.h>
#include <math.h>
#include <stdint.h>

#define BB 2
#define LL 2048
#define DM 1024
#define NH 16
#define HD 64
#define DFF 4096
#define NTOK (BB*LL)
#define LN_EPS 1e-5f

// ---------------- scratch (no allocation allowed) ----------------
__device__ float g_xn [NTOK*DM];
__device__ float g_q  [NTOK*DM];
__device__ float g_k  [NTOK*DM];
__device__ float g_v  [NTOK*DM];
__device__ float g_o  [NTOK*DM];
__device__ float g_x2 [NTOK*DM];
__device__ float g_xn2[NTOK*DM];
__device__ float g_h  [NTOK*DFF];

// ---------------- helpers ----------------
__device__ __forceinline__ void cp16(void* smem, const void* g) {
    unsigned sa = (unsigned)__cvta_generic_to_shared(smem);
    asm volatile("cp.async.cg.shared.global [%0], [%1], 16;" :: "r"(sa), "l"(g));
}
#define CP_COMMIT() asm volatile("cp.async.commit_group;" ::: "memory")
#define CP_WAIT0()  asm volatile("cp.async.wait_group 0;" ::: "memory")

__device__ __forceinline__ uint32_t to_tf32(float x) {
    uint32_t r;
    asm("cvt.rna.tf32.f32 %0, %1;" : "=r"(r) : "f"(x));
    return r;
}
__device__ __forceinline__ void mma8(float& c0, float& c1, float& c2, float& c3,
                                     uint32_t a0, uint32_t a1, uint32_t a2, uint32_t a3,
                                     uint32_t b0, uint32_t b1) {
    asm("mma.sync.aligned.m16n8k8.row.col.f32.tf32.tf32.f32 "
        "{%0,%1,%2,%3},{%4,%5,%6,%7},{%8,%9},{%0,%1,%2,%3};"
        : "+f"(c0), "+f"(c1), "+f"(c2), "+f"(c3)
        : "r"(a0), "r"(a1), "r"(a2), "r"(a3), "r"(b0), "r"(b1));
}

// ---------------- LayerNorm ----------------
__global__ void ln_kernel(const float* __restrict__ x, const float* __restrict__ g,
                          const float* __restrict__ b, float* __restrict__ y)
{
    int row = blockIdx.x;
    int t = threadIdx.x;
    const float4* xr = (const float4*)(x + (size_t)row * DM);
    float4 v = xr[t];
    float s  = v.x + v.y + v.z + v.w;
    float ss = v.x*v.x + v.y*v.y + v.z*v.z + v.w*v.w;
#pragma unroll
    for (int o = 16; o; o >>= 1) {
        s  += __shfl_xor_sync(0xffffffffu, s,  o);
        ss += __shfl_xor_sync(0xffffffffu, ss, o);
    }
    __shared__ float sh_s[8], sh_ss[8];
    int w = t >> 5, lane = t & 31;
    if (lane == 0) { sh_s[w] = s; sh_ss[w] = ss; }
    __syncthreads();
    if (t < 32) {
        s  = (t < 8) ? sh_s[t]  : 0.f;
        ss = (t < 8) ? sh_ss[t] : 0.f;
#pragma unroll
        for (int o = 4; o; o >>= 1) {
            s  += __shfl_xor_sync(0xffffffffu, s,  o);
            ss += __shfl_xor_sync(0xffffffffu, ss, o);
        }
        if (t == 0) { sh_s[0] = s; sh_ss[0] = ss; }
    }
    __syncthreads();
    float mu  = sh_s[0] * (1.f / DM);
    float var = sh_ss[0] * (1.f / DM) - mu * mu;
    float inv = rsqrtf(var + LN_EPS);
    float4 gv = ((const float4*)g)[t];
    float4 bv = ((const float4*)b)[t];
    float4 o4;
    o4.x = (v.x - mu) * inv * gv.x + bv.x;
    o4.y = (v.y - mu) * inv * gv.y + bv.y;
    o4.z = (v.z - mu) * inv * gv.z + bv.z;
    o4.w = (v.w - mu) * inv * gv.w + bv.w;
    ((float4*)(y + (size_t)row * DM))[t] = o4;
}

// ---------------- RoPE (heads < 8) + q scale (all heads) ----------------
__global__ void rope_kernel(float* __restrict__ q, float* __restrict__ k)
{
    int idx = blockIdx.x * blockDim.x + threadIdx.x;
    const int total = NTOK * NH * (HD / 2);
    if (idx >= total) return;
    int i   = idx & 31;
    int h   = (idx >> 5) & 15;
    int tok = idx >> 9;
    int l   = tok & (LL - 1);
    size_t base = (size_t)tok * DM + h * HD + 2 * i;

    float q1 = q[base], q2 = q[base + 1];
    if (h < 8) {
        double invf = pow(10000.0, -(double)i / 32.0);
        float ang_unused = 0.f; (void)ang_unused;
        double ang = (double)l * invf;
        float cs = (float)cos(ang);
        float sn = (float)sin(ang);
        float qe = q1 * cs - q2 * sn;
        float qo = q1 * sn + q2 * cs;
        q1 = qe; q2 = qo;
        float k1 = k[base], k2 = k[base + 1];
        k[base]     = k1 * cs - k2 * sn;
        k[base + 1] = k1 * sn + k2 * cs;
    }
    q[base]     = q1 * 0.125f;
    q[base + 1] = q2 * 0.125f;
}

// ---------------- tf32 tensor-core GEMM ----------------
// C[M,N] = A[M,K] @ B[K,N] + bias (+res) (relu)
// 128x128 tile, BK=32, 256 threads = 8 warps (2m x 4n), warp tile 64x32.
// As: [128][36] (row-major, pad 4 -> conflict-free a-frag loads: 4g+t)
// Bs: [32][136]  (row-major, pad 8 -> conflict-free b-frag loads: 8t+g)
#define GA_STRIDE 36
#define GB_STRIDE 136
#define GA_FLOATS (128*GA_STRIDE)   // 4608
#define GB_FLOATS (32*GB_STRIDE)    // 4352
#define GEMM_SMEM ((2*GA_FLOATS + 2*GB_FLOATS)*4)  // 71680 bytes

template<bool RELU, bool RES>
__global__ __launch_bounds__(256, 2)
void tgemm(const float* __restrict__ A, const float* __restrict__ Bm,
           const float* __restrict__ bias, const float* __restrict__ res,
           float* __restrict__ C, int M, int N, int K)
{
    extern __shared__ float dsm[];
    float* As[2] = { dsm,                dsm + GA_FLOATS };
    float* Bs[2] = { dsm + 2*GA_FLOATS,  dsm + 2*GA_FLOATS + GB_FLOATS };

    int t = threadIdx.x;
    int wid = t >> 5, lane = t & 31;
    int g = lane >> 2, tq = lane & 3;
    int m0 = blockIdx.y * 128, n0 = blockIdx.x * 128;
    int wm = (wid >> 2) * 64;   // 0 or 64
    int wn = (wid & 3) * 32;    // 0,32,64,96

    float acc[4][4][4];
#pragma unroll
    for (int i = 0; i < 4; i++)
#pragma unroll
        for (int j = 0; j < 4; j++)
#pragma unroll
            for (int c = 0; c < 4; c++) acc[i][j][c] = 0.f;

    // prologue: slab 0
#pragma unroll
    for (int u = 0; u < 4; u++) {
        int i = t + u * 256;
        int am = i >> 3, ak4 = i & 7;
        cp16(&As[0][am*GA_STRIDE + ak4*4], A + (size_t)(m0 + am) * K + ak4 * 4);
        int bk = i >> 5, bn4 = i & 31;
        cp16(&Bs[0][bk*GB_STRIDE + bn4*4], Bm + (size_t)bk * N + n0 + bn4 * 4);
    }
    CP_COMMIT(); CP_WAIT0(); __syncthreads();

    int NK = K >> 5;
    for (int k0 = 0; k0 < NK; k0++) {
        int cur = k0 & 1;
        if (k0 + 1 < NK) {
            int nxt = cur ^ 1;
            int kb = (k0 + 1) << 5;
#pragma unroll
            for (int u = 0; u < 4; u++) {
                int i = t + u * 256;
                int am = i >> 3, ak4 = i & 7;
                cp16(&As[nxt][am*GA_STRIDE + ak4*4], A + (size_t)(m0 + am) * K + kb + ak4 * 4);
                int bk = i >> 5, bn4 = i & 31;
                cp16(&Bs[nxt][bk*GB_STRIDE + bn4*4], Bm + (size_t)(kb + bk) * N + n0 + bn4 * 4);
            }
        }
        CP_COMMIT();

        const float* as = As[cur];
        const float* bs = Bs[cur];
#pragma unroll
        for (int kf = 0; kf < 4; kf++) {
            uint32_t bf[4][2];
#pragma unroll
            for (int nf = 0; nf < 4; nf++) {
                bf[nf][0] = to_tf32(bs[(kf*8 + tq)    *GB_STRIDE + wn + nf*8 + g]);
                bf[nf][1] = to_tf32(bs[(kf*8 + tq + 4)*GB_STRIDE + wn + nf*8 + g]);
            }
#pragma unroll
            for (int mf = 0; mf < 4; mf++) {
                int row = wm + mf * 16;
                uint32_t a0 = to_tf32(as[(row + g)    *GA_STRIDE + kf*8 + tq]);
                uint32_t a1 = to_tf32(as[(row + g + 8)*GA_STRIDE + kf*8 + tq]);
                uint32_t a2 = to_tf32(as[(row + g)    *GA_STRIDE + kf*8 + tq + 4]);
                uint32_t a3 = to_tf32(as[(row + g + 8)*GA_STRIDE + kf*8 + tq + 4]);
#pragma unroll
                for (int nf = 0; nf < 4; nf++)
                    mma8(acc[mf][nf][0], acc[mf][nf][1], acc[mf][nf][2], acc[mf][nf][3],
                         a0, a1, a2, a3, bf[nf][0], bf[nf][1]);
            }
        }
        CP_WAIT0(); __syncthreads();
    }

    // epilogue
#pragma unroll
    for (int mf = 0; mf < 4; mf++) {
#pragma unroll
        for (int nf = 0; nf < 4; nf++) {
            int r0 = m0 + wm + mf*16 + g;
            int r1 = r0 + 8;
            int cN = n0 + wn + nf*8 + 2*tq;
            float b0v = bias[cN], b1v = bias[cN + 1];
            float v0 = acc[mf][nf][0] + b0v;
            float v1 = acc[mf][nf][1] + b1v;
            float v2 = acc[mf][nf][2] + b0v;
            float v3 = acc[mf][nf][3] + b1v;
            if (RES) {
                v0 += res[(size_t)r0 * N + cN];     v1 += res[(size_t)r0 * N + cN + 1];
                v2 += res[(size_t)r1 * N + cN];     v3 += res[(size_t)r1 * N + cN + 1];
            }
            if (RELU) {
                v0 = fmaxf(v0, 0.f); v1 = fmaxf(v1, 0.f);
                v2 = fmaxf(v2, 0.f); v3 = fmaxf(v3, 0.f);
            }
            *(float2*)(C + (size_t)r0 * N + cN) = make_float2(v0, v1);
            *(float2*)(C + (size_t)r1 * N + cN) = make_float2(v2, v3);
        }
    }
}

// ---------------- tf32 flash attention ----------------
// 64 q-rows per block, 128 threads = 4 warps, each warp 16 rows.
// Qs [64][68], Ks[2][64][68], Vs[2][64][72], Ps [64][68]
#define AQ_STRIDE 68
#define AV_STRIDE 72
#define AQ_FLOATS (64*AQ_STRIDE)   // 4352
#define AV_FLOATS (64*AV_STRIDE)   // 4608
#define ATTN_SMEM ((AQ_FLOATS + 2*AQ_FLOATS + 2*AV_FLOATS + AQ_FLOATS)*4)  // 106496

__global__ __launch_bounds__(128, 2)
void attn_kernel(const float* __restrict__ q, const float* __restrict__ k,
                 const float* __restrict__ v, float* __restrict__ o)
{
    extern __shared__ float sm[];
    float* Qs = sm;
    float* Ks[2] = { sm + AQ_FLOATS, sm + 2*AQ_FLOATS };
    float* Vs[2] = { sm + 3*AQ_FLOATS, sm + 3*AQ_FLOATS + AV_FLOATS };
    float* Ps = sm + 3*AQ_FLOATS + 2*AV_FLOATS;

    int qt = blockIdx.x, h = blockIdx.y, b = blockIdx.z;
    int t = threadIdx.x;
    int wid = t >> 5, lane = t & 31;
    int g = lane >> 2, tq = lane & 3;
    int wq = wid * 16;

    const float* qbh = q + ((size_t)b * LL + qt * 64) * DM + h * HD;
    const float* kbh = k + (size_t)b * LL * DM + h * HD;
    const float* vbh = v + (size_t)b * LL * DM + h * HD;

    // load Q tile + KV tile 0
#pragma unroll
    for (int u = 0; u < 8; u++) {
        int i = t + u * 128;
        int rr = i >> 4, c4 = i & 15;
        cp16(&Qs[rr*AQ_STRIDE + c4*4], qbh + (size_t)rr * DM + c4 * 4);
    }
#pragma unroll
    for (int u = 0; u < 8; u++) {
        int i = t + u * 128;
        int rr = i >> 4, c4 = i & 15;
        cp16(&Ks[0][rr*AQ_STRIDE + c4*4], kbh + (size_t)rr * DM + c4 * 4);
        cp16(&Vs[0][rr*AV_STRIDE + c4*4], vbh + (size_t)rr * DM + c4 * 4);
    }
    CP_COMMIT(); CP_WAIT0(); __syncthreads();

    float oacc[8][4];
#pragma unroll
    for (int i = 0; i < 8; i++)
#pragma unroll
        for (int c = 0; c < 4; c++) oacc[i][c] = 0.f;
    float m0 = -1e30f, m1 = -1e30f, l0 = 0.f, l1 = 0.f;

    for (int j = 0; j < LL/64; j++) {
        int cur = j & 1;
        if (j + 1 < LL/64) {
            int nxt = cur ^ 1;
            const float* kn = kbh + (size_t)(j + 1) * 64 * DM;
            const float* vn = vbh + (size_t)(j + 1) * 64 * DM;
#pragma unroll
            for (int u = 0; u < 8; u++) {
                int i = t + u * 128;
                int rr = i >> 4, c4 = i & 15;
                cp16(&Ks[nxt][rr*AQ_STRIDE + c4*4], kn + (size_t)rr * DM + c4 * 4);
                cp16(&Vs[nxt][rr*AV_STRIDE + c4*4], vn + (size_t)rr * DM + c4 * 4);
            }
        }
        CP_COMMIT();

        const float* ks = Ks[cur];
        const float* vs = Vs[cur];

        // ---- S = Q @ K^T ----
        float sacc[8][4];
#pragma unroll
        for (int i = 0; i < 8; i++)
#pragma unroll
            for (int c = 0; c < 4; c++) sacc[i][c] = 0.f;

#pragma unroll
        for (int kf = 0; kf < 8; kf++) {
            uint32_t a0 = to_tf32(Qs[(wq + g)    *AQ_STRIDE + kf*8 + tq]);
            uint32_t a1 = to_tf32(Qs[(wq + g + 8)*AQ_STRIDE + kf*8 + tq]);
            uint32_t a2 = to_tf32(Qs[(wq + g)    *AQ_STRIDE + kf*8 + tq + 4]);
            uint32_t a3 = to_tf32(Qs[(wq + g + 8)*AQ_STRIDE + kf*8 + tq + 4]);
#pragma unroll
            for (int nf = 0; nf < 8; nf++) {
                uint32_t b0 = to_tf32(ks[(nf*8 + g)*AQ_STRIDE + kf*8 + tq]);
                uint32_t b1 = to_tf32(ks[(nf*8 + g)*AQ_STRIDE + kf*8 + tq + 4]);
                mma8(sacc[nf][0], sacc[nf][1], sacc[nf][2], sacc[nf][3],
                     a0, a1, a2, a3, b0, b1);
            }
        }

        // ---- online softmax (rows wq+g and wq+g+8) ----
        float mx0 = -1e30f, mx1 = -1e30f;
#pragma unroll
        for (int nf = 0; nf < 8; nf++) {
            mx0 = fmaxf(mx0, fmaxf(sacc[nf][0], sacc[nf][1]));
            mx1 = fmaxf(mx1, fmaxf(sacc[nf][2], sacc[nf][3]));
        }
        mx0 = fmaxf(mx0, __shfl_xor_sync(0xffffffffu, mx0, 1));
        mx0 = fmaxf(mx0, __shfl_xor_sync(0xffffffffu, mx0, 2));
        mx1 = fmaxf(mx1, __shfl_xor_sync(0xffffffffu, mx1, 1));
        mx1 = fmaxf(mx1, __shfl_xor_sync(0xffffffffu, mx1, 2));
        float mn0 = fmaxf(m0, mx0), mn1 = fmaxf(m1, mx1);
        float al0 = __expf(m0 - mn0), al1 = __expf(m1 - mn1);

        __syncwarp();   // prior tile's P reads are done before overwriting

        float sum0 = 0.f, sum1 = 0.f;
#pragma unroll
        for (int nf = 0; nf < 8; nf++) {
            float p0 = __expf(sacc[nf][0] - mn0);
            float p1 = __expf(sacc[nf][1] - mn0);
            float p2 = __expf(sacc[nf][2] - mn1);
            float p3 = __expf(sacc[nf][3] - mn1);
            sum0 += p0 + p1;
            sum1 += p2 + p3;
            *(float2*)(&Ps[(wq + g)    *AQ_STRIDE + nf*8 + 2*tq]) = make_float2(p0, p1);
            *(float2*)(&Ps[(wq + g + 8)*AQ_STRIDE + nf*8 + 2*tq]) = make_float2(p2, p3);
        }
        sum0 += __shfl_xor_sync(0xffffffffu, sum0, 1);
        sum0 += __shfl_xor_sync(0xffffffffu, sum0, 2);
        sum1 += __shfl_xor_sync(0xffffffffu, sum1, 1);
        sum1 += __shfl_xor_sync(0xffffffffu, sum1, 2);
        l0 = l0 * al0 + sum0;
        l1 = l1 * al1 + sum1;
        m0 = mn0; m1 = mn1;
#pragma unroll
        for (int nf = 0; nf < 8; nf++) {
            oacc[nf][0] *= al0; oacc[nf][1] *= al0;
            oacc[nf][2] *= al1; oacc[nf][3] *= al1;
        }
        __syncwarp();   // P visible to all lanes of this warp

        // ---- O += P @ V ----
#pragma unroll
        for (int kf = 0; kf < 8; kf++) {
            uint32_t a0 = to_tf32(Ps[(wq + g)    *AQ_STRIDE + kf*8 + tq]);
            uint32_t a1 = to_tf32(Ps[(wq + g + 8)*AQ_STRIDE + kf*8 + tq]);
            uint32_t a2 = to_tf32(Ps[(wq + g)    *AQ_STRIDE + kf*8 + tq + 4]);
            uint32_t a3 = to_tf32(Ps[(wq + g + 8)*AQ_STRIDE + kf*8 + tq + 4]);
#pragma unroll
            for (int nf = 0; nf < 8; nf++) {
                uint32_t b0 = to_tf32(vs[(kf*8 + tq)    *AV_STRIDE + nf*8 + g]);
                uint32_t b1 = to_tf32(vs[(kf*8 + tq + 4)*AV_STRIDE + nf*8 + g]);
                mma8(oacc[nf][0], oacc[nf][1], oacc[nf][2], oacc[nf][3],
                     a0, a1, a2, a3, b0, b1);
            }
        }

        CP_WAIT0();
        __syncthreads();
    }

    float inv0 = 1.f / l0, inv1 = 1.f / l1;
    size_t row0 = (size_t)b * LL + qt * 64 + wq + g;
    size_t row1 = row0 + 8;
#pragma unroll
    for (int nf = 0; nf < 8; nf++) {
        int cN = h * HD + nf*8 + 2*tq;
        *(float2*)(o + row0 * DM + cN) = make_float2(oacc[nf][0] * inv0, oacc[nf][1] * inv0);
        *(float2*)(o + row1 * DM + cN) = make_float2(oacc[nf][2] * inv1, oacc[nf][3] * inv1);
    }
}

// ---------------- launcher ----------------
extern "C" void kernel_launch(void* const* d_in, const int* in_sizes, int n_in,
                              void* d_out, int out_size)
{
    const float* x     = (const float*)d_in[0];
    const float* Wq    = (const float*)d_in[1];
    const float* bq    = (const float*)d_in[2];
    const float* Wk    = (const float*)d_in[3];
    const float* bk    = (const float*)d_in[4];
    const float* Wv    = (const float*)d_in[5];
    const float* bv    = (const float*)d_in[6];
    const float* Wo    = (const float*)d_in[7];
    const float* bo    = (const float*)d_in[8];
    const float* ln1_g = (const float*)d_in[9];
    const float* ln1_b = (const float*)d_in[10];
    const float* ln2_g = (const float*)d_in[11];
    const float* ln2_b = (const float*)d_in[12];
    const float* W1    = (const float*)d_in[13];
    const float* b1    = (const float*)d_in[14];
    const float* W2    = (const float*)d_in[15];
    const float* b2    = (const float*)d_in[16];
    float* out = (float*)d_out;

    float *xn, *q, *k, *v, *o, *x2, *xn2, *hb;
    cudaGetSymbolAddress((void**)&xn,  g_xn);
    cudaGetSymbolAddress((void**)&q,   g_q);
    cudaGetSymbolAddress((void**)&k,   g_k);
    cudaGetSymbolAddress((void**)&v,   g_v);
    cudaGetSymbolAddress((void**)&o,   g_o);
    cudaGetSymbolAddress((void**)&x2,  g_x2);
    cudaGetSymbolAddress((void**)&xn2, g_xn2);
    cudaGetSymbolAddress((void**)&hb,  g_h);

    static bool attr_set = false;
    if (!attr_set) {
        cudaFuncSetAttribute(tgemm<false,false>, cudaFuncAttributeMaxDynamicSharedMemorySize, GEMM_SMEM);
        cudaFuncSetAttribute(tgemm<false,true>,  cudaFuncAttributeMaxDynamicSharedMemorySize, GEMM_SMEM);
        cudaFuncSetAttribute(tgemm<true,false>,  cudaFuncAttributeMaxDynamicSharedMemorySize, GEMM_SMEM);
        cudaFuncSetAttribute(attn_kernel, cudaFuncAttributeMaxDynamicSharedMemorySize, ATTN_SMEM);
        attr_set = true;
    }

    ln_kernel<<<NTOK, 256>>>(x, ln1_g, ln1_b, xn);

    dim3 g1(DM / 128, NTOK / 128);     // (8, 32)
    tgemm<false,false><<<g1, 256, GEMM_SMEM>>>(xn, Wq, bq, nullptr, q, NTOK, DM, DM);
    tgemm<false,false><<<g1, 256, GEMM_SMEM>>>(x,  Wk, bk, nullptr, k, NTOK, DM, DM);
    tgemm<false,false><<<g1, 256, GEMM_SMEM>>>(x,  Wv, bv, nullptr, v, NTOK, DM, DM);

    const int pairs = NTOK * NH * (HD / 2);
    rope_kernel<<<(pairs + 255) / 256, 256>>>(q, k);

    dim3 ga(LL / 64, NH, BB);          // (32, 16, 2)
    attn_kernel<<<ga, 128, ATTN_SMEM>>>(q, k, v, o);

    tgemm<false,true><<<g1, 256, GEMM_SMEM>>>(o, Wo, bo, x, x2, NTOK, DM, DM);

    ln_kernel<<<NTOK, 256>>>(x2, ln2_g, ln2_b, xn2);

    dim3 g2(DFF / 128, NTOK / 128);    // (32, 32)
    tgemm<true,false><<<g2, 256, GEMM_SMEM>>>(xn2, W1, b1, nullptr, hb, NTOK, DFF, DM);
    tgemm<false,true><<<g1, 256, GEMM_SMEM>>>(hb, W2, b2, x2, out, NTOK, DM, DFF);
}

// round 4
// speedup vs baseline: 8.5770x; 1.0849x over previous
#include <cuda_runtime.h>
#include <math.h>
#include <stdint.h>

#define BB 2
#define LL 2048
#define DM 1024
#define NH 16
#define HD 64
#define DFF 4096
#define NTOK (BB*LL)
#define LN_EPS 1e-5f

// ---------------- scratch (no allocation allowed) ----------------
__device__ float g_xn [NTOK*DM];
__device__ float g_q  [NTOK*DM];
__device__ float g_k  [NTOK*DM];
__device__ float g_v  [NTOK*DM];
__device__ float g_o  [NTOK*DM];
__device__ float g_x2 [NTOK*DM];
__device__ float g_xn2[NTOK*DM];
__device__ float g_h  [NTOK*DFF];
// tf32-rounded copies of external operands
__device__ float g_xr [NTOK*DM];
__device__ float g_wq [DM*DM];
__device__ float g_wk [DM*DM];
__device__ float g_wv [DM*DM];
__device__ float g_wo [DM*DM];
__device__ float g_w1 [DM*DFF];
__device__ float g_w2 [DFF*DM];

// ---------------- helpers ----------------
__device__ __forceinline__ void cp16(void* smem, const void* g) {
    unsigned sa = (unsigned)__cvta_generic_to_shared(smem);
    asm volatile("cp.async.cg.shared.global [%0], [%1], 16;" :: "r"(sa), "l"(g));
}
#define CP_COMMIT() asm volatile("cp.async.commit_group;" ::: "memory")
#define CP_WAIT0()  asm volatile("cp.async.wait_group 0;" ::: "memory")

__device__ __forceinline__ uint32_t to_tf32(float x) {
    uint32_t r;
    asm("cvt.rna.tf32.f32 %0, %1;" : "=r"(r) : "f"(x));
    return r;
}
__device__ __forceinline__ float tf32f(float x) {
    return __uint_as_float(to_tf32(x));
}
__device__ __forceinline__ void mma8(float& c0, float& c1, float& c2, float& c3,
                                     uint32_t a0, uint32_t a1, uint32_t a2, uint32_t a3,
                                     uint32_t b0, uint32_t b1) {
    asm("mma.sync.aligned.m16n8k8.row.col.f32.tf32.tf32.f32 "
        "{%0,%1,%2,%3},{%4,%5,%6,%7},{%8,%9},{%0,%1,%2,%3};"
        : "+f"(c0), "+f"(c1), "+f"(c2), "+f"(c3)
        : "r"(a0), "r"(a1), "r"(a2), "r"(a3), "r"(b0), "r"(b1));
}

// ---------------- tf32 rounding pass ----------------
__global__ void round_tf32_kernel(const float* __restrict__ in, float* __restrict__ out, int n4)
{
    int i = blockIdx.x * blockDim.x + threadIdx.x;
    if (i >= n4) return;
    float4 v = ((const float4*)in)[i];
    v.x = tf32f(v.x); v.y = tf32f(v.y); v.z = tf32f(v.z); v.w = tf32f(v.w);
    ((float4*)out)[i] = v;
}

// ---------------- LayerNorm (output rounded to tf32) ----------------
__global__ void ln_kernel(const float* __restrict__ x, const float* __restrict__ g,
                          const float* __restrict__ b, float* __restrict__ y)
{
    int row = blockIdx.x;
    int t = threadIdx.x;
    const float4* xr = (const float4*)(x + (size_t)row * DM);
    float4 v = xr[t];
    float s  = v.x + v.y + v.z + v.w;
    float ss = v.x*v.x + v.y*v.y + v.z*v.z + v.w*v.w;
#pragma unroll
    for (int o = 16; o; o >>= 1) {
        s  += __shfl_xor_sync(0xffffffffu, s,  o);
        ss += __shfl_xor_sync(0xffffffffu, ss, o);
    }
    __shared__ float sh_s[8], sh_ss[8];
    int w = t >> 5, lane = t & 31;
    if (lane == 0) { sh_s[w] = s; sh_ss[w] = ss; }
    __syncthreads();
    if (t < 32) {
        s  = (t < 8) ? sh_s[t]  : 0.f;
        ss = (t < 8) ? sh_ss[t] : 0.f;
#pragma unroll
        for (int o = 4; o; o >>= 1) {
            s  += __shfl_xor_sync(0xffffffffu, s,  o);
            ss += __shfl_xor_sync(0xffffffffu, ss, o);
        }
        if (t == 0) { sh_s[0] = s; sh_ss[0] = ss; }
    }
    __syncthreads();
    float mu  = sh_s[0] * (1.f / DM);
    float var = sh_ss[0] * (1.f / DM) - mu * mu;
    float inv = rsqrtf(var + LN_EPS);
    float4 gv = ((const float4*)g)[t];
    float4 bv = ((const float4*)b)[t];
    float4 o4;
    o4.x = tf32f((v.x - mu) * inv * gv.x + bv.x);
    o4.y = tf32f((v.y - mu) * inv * gv.y + bv.y);
    o4.z = tf32f((v.z - mu) * inv * gv.z + bv.z);
    o4.w = tf32f((v.w - mu) * inv * gv.w + bv.w);
    ((float4*)(y + (size_t)row * DM))[t] = o4;
}

// ---------------- RoPE (heads < 8) + q scale (all heads), tf32-rounded out ----------------
__global__ void rope_kernel(float* __restrict__ q, float* __restrict__ k)
{
    int idx = blockIdx.x * blockDim.x + threadIdx.x;
    const int total = NTOK * NH * (HD / 2);
    if (idx >= total) return;
    int i   = idx & 31;
    int h   = (idx >> 5) & 15;
    int tok = idx >> 9;
    int l   = tok & (LL - 1);
    size_t base = (size_t)tok * DM + h * HD + 2 * i;

    float q1 = q[base], q2 = q[base + 1];
    if (h < 8) {
        double invf = pow(10000.0, -(double)i / 32.0);
        double ang = (double)l * invf;
        float cs = (float)cos(ang);
        float sn = (float)sin(ang);
        float qe = q1 * cs - q2 * sn;
        float qo = q1 * sn + q2 * cs;
        q1 = qe; q2 = qo;
        float k1 = k[base], k2 = k[base + 1];
        k[base]     = tf32f(k1 * cs - k2 * sn);
        k[base + 1] = tf32f(k1 * sn + k2 * cs);
    }
    q[base]     = tf32f(q1 * 0.125f);
    q[base + 1] = tf32f(q2 * 0.125f);
}

// ---------------- tf32 tensor-core GEMM (inputs pre-rounded; no cvt in loop) ----------------
// C[M,N] = A[M,K] @ B[K,N] + bias (+res) (relu) (round)
// 128x128 tile, BK=32, 256 threads = 8 warps (2m x 4n), warp tile 64x32.
#define GA_STRIDE 36
#define GB_STRIDE 136
#define GA_FLOATS (128*GA_STRIDE)
#define GB_FLOATS (32*GB_STRIDE)
#define GEMM_SMEM ((2*GA_FLOATS + 2*GB_FLOATS)*4)

template<bool RELU, bool RES, bool ROUND>
__global__ __launch_bounds__(256, 2)
void tgemm(const float* __restrict__ A, const float* __restrict__ Bm,
           const float* __restrict__ bias, const float* __restrict__ res,
           float* __restrict__ C, int M, int N, int K)
{
    extern __shared__ float dsm[];
    float* As[2] = { dsm,                dsm + GA_FLOATS };
    float* Bs[2] = { dsm + 2*GA_FLOATS,  dsm + 2*GA_FLOATS + GB_FLOATS };

    int t = threadIdx.x;
    int wid = t >> 5, lane = t & 31;
    int g = lane >> 2, tq = lane & 3;
    int m0 = blockIdx.y * 128, n0 = blockIdx.x * 128;
    int wm = (wid >> 2) * 64;
    int wn = (wid & 3) * 32;

    float acc[4][4][4];
#pragma unroll
    for (int i = 0; i < 4; i++)
#pragma unroll
        for (int j = 0; j < 4; j++)
#pragma unroll
            for (int c = 0; c < 4; c++) acc[i][j][c] = 0.f;

#pragma unroll
    for (int u = 0; u < 4; u++) {
        int i = t + u * 256;
        int am = i >> 3, ak4 = i & 7;
        cp16(&As[0][am*GA_STRIDE + ak4*4], A + (size_t)(m0 + am) * K + ak4 * 4);
        int bk = i >> 5, bn4 = i & 31;
        cp16(&Bs[0][bk*GB_STRIDE + bn4*4], Bm + (size_t)bk * N + n0 + bn4 * 4);
    }
    CP_COMMIT(); CP_WAIT0(); __syncthreads();

    int NK = K >> 5;
    for (int k0 = 0; k0 < NK; k0++) {
        int cur = k0 & 1;
        if (k0 + 1 < NK) {
            int nxt = cur ^ 1;
            int kb = (k0 + 1) << 5;
#pragma unroll
            for (int u = 0; u < 4; u++) {
                int i = t + u * 256;
                int am = i >> 3, ak4 = i & 7;
                cp16(&As[nxt][am*GA_STRIDE + ak4*4], A + (size_t)(m0 + am) * K + kb + ak4 * 4);
                int bk = i >> 5, bn4 = i & 31;
                cp16(&Bs[nxt][bk*GB_STRIDE + bn4*4], Bm + (size_t)(kb + bk) * N + n0 + bn4 * 4);
            }
        }
        CP_COMMIT();

        const uint32_t* as = (const uint32_t*)As[cur];
        const uint32_t* bs = (const uint32_t*)Bs[cur];
#pragma unroll
        for (int kf = 0; kf < 4; kf++) {
            uint32_t bf[4][2];
#pragma unroll
            for (int nf = 0; nf < 4; nf++) {
                bf[nf][0] = bs[(kf*8 + tq)    *GB_STRIDE + wn + nf*8 + g];
                bf[nf][1] = bs[(kf*8 + tq + 4)*GB_STRIDE + wn + nf*8 + g];
            }
#pragma unroll
            for (int mf = 0; mf < 4; mf++) {
                int row = wm + mf * 16;
                uint32_t a0 = as[(row + g)    *GA_STRIDE + kf*8 + tq];
                uint32_t a1 = as[(row + g + 8)*GA_STRIDE + kf*8 + tq];
                uint32_t a2 = as[(row + g)    *GA_STRIDE + kf*8 + tq + 4];
                uint32_t a3 = as[(row + g + 8)*GA_STRIDE + kf*8 + tq + 4];
#pragma unroll
                for (int nf = 0; nf < 4; nf++)
                    mma8(acc[mf][nf][0], acc[mf][nf][1], acc[mf][nf][2], acc[mf][nf][3],
                         a0, a1, a2, a3, bf[nf][0], bf[nf][1]);
            }
        }
        CP_WAIT0(); __syncthreads();
    }

#pragma unroll
    for (int mf = 0; mf < 4; mf++) {
#pragma unroll
        for (int nf = 0; nf < 4; nf++) {
            int r0 = m0 + wm + mf*16 + g;
            int r1 = r0 + 8;
            int cN = n0 + wn + nf*8 + 2*tq;
            float b0v = bias[cN], b1v = bias[cN + 1];
            float v0 = acc[mf][nf][0] + b0v;
            float v1 = acc[mf][nf][1] + b1v;
            float v2 = acc[mf][nf][2] + b0v;
            float v3 = acc[mf][nf][3] + b1v;
            if (RES) {
                v0 += res[(size_t)r0 * N + cN];     v1 += res[(size_t)r0 * N + cN + 1];
                v2 += res[(size_t)r1 * N + cN];     v3 += res[(size_t)r1 * N + cN + 1];
            }
            if (RELU) {
                v0 = fmaxf(v0, 0.f); v1 = fmaxf(v1, 0.f);
                v2 = fmaxf(v2, 0.f); v3 = fmaxf(v3, 0.f);
            }
            if (ROUND) {
                v0 = tf32f(v0); v1 = tf32f(v1); v2 = tf32f(v2); v3 = tf32f(v3);
            }
            *(float2*)(C + (size_t)r0 * N + cN) = make_float2(v0, v1);
            *(float2*)(C + (size_t)r1 * N + cN) = make_float2(v2, v3);
        }
    }
}

// ---------------- tf32 flash attention (inputs pre-rounded) ----------------
#define AQ_STRIDE 68
#define AV_STRIDE 72
#define AQ_FLOATS (64*AQ_STRIDE)
#define AV_FLOATS (64*AV_STRIDE)
#define ATTN_SMEM ((AQ_FLOATS + 2*AQ_FLOATS + 2*AV_FLOATS + AQ_FLOATS)*4)

__global__ __launch_bounds__(128, 2)
void attn_kernel(const float* __restrict__ q, const float* __restrict__ k,
                 const float* __restrict__ v, float* __restrict__ o)
{
    extern __shared__ float sm[];
    float* Qs = sm;
    float* Ks[2] = { sm + AQ_FLOATS, sm + 2*AQ_FLOATS };
    float* Vs[2] = { sm + 3*AQ_FLOATS, sm + 3*AQ_FLOATS + AV_FLOATS };
    float* Ps = sm + 3*AQ_FLOATS + 2*AV_FLOATS;

    int qt = blockIdx.x, h = blockIdx.y, b = blockIdx.z;
    int t = threadIdx.x;
    int wid = t >> 5, lane = t & 31;
    int g = lane >> 2, tq = lane & 3;
    int wq = wid * 16;

    const float* qbh = q + ((size_t)b * LL + qt * 64) * DM + h * HD;
    const float* kbh = k + (size_t)b * LL * DM + h * HD;
    const float* vbh = v + (size_t)b * LL * DM + h * HD;

#pragma unroll
    for (int u = 0; u < 8; u++) {
        int i = t + u * 128;
        int rr = i >> 4, c4 = i & 15;
        cp16(&Qs[rr*AQ_STRIDE + c4*4], qbh + (size_t)rr * DM + c4 * 4);
    }
#pragma unroll
    for (int u = 0; u < 8; u++) {
        int i = t + u * 128;
        int rr = i >> 4, c4 = i & 15;
        cp16(&Ks[0][rr*AQ_STRIDE + c4*4], kbh + (size_t)rr * DM + c4 * 4);
        cp16(&Vs[0][rr*AV_STRIDE + c4*4], vbh + (size_t)rr * DM + c4 * 4);
    }
    CP_COMMIT(); CP_WAIT0(); __syncthreads();

    // hoist Q fragments into registers (loop-invariant)
    uint32_t qa[8][4];
    {
        const uint32_t* qsu = (const uint32_t*)Qs;
#pragma unroll
        for (int kf = 0; kf < 8; kf++) {
            qa[kf][0] = qsu[(wq + g)    *AQ_STRIDE + kf*8 + tq];
            qa[kf][1] = qsu[(wq + g + 8)*AQ_STRIDE + kf*8 + tq];
            qa[kf][2] = qsu[(wq + g)    *AQ_STRIDE + kf*8 + tq + 4];
            qa[kf][3] = qsu[(wq + g + 8)*AQ_STRIDE + kf*8 + tq + 4];
        }
    }

    float oacc[8][4];
#pragma unroll
    for (int i = 0; i < 8; i++)
#pragma unroll
        for (int c = 0; c < 4; c++) oacc[i][c] = 0.f;
    float m0 = -1e30f, m1 = -1e30f, l0 = 0.f, l1 = 0.f;

    for (int j = 0; j < LL/64; j++) {
        int cur = j & 1;
        if (j + 1 < LL/64) {
            int nxt = cur ^ 1;
            const float* kn = kbh + (size_t)(j + 1) * 64 * DM;
            const float* vn = vbh + (size_t)(j + 1) * 64 * DM;
#pragma unroll
            for (int u = 0; u < 8; u++) {
                int i = t + u * 128;
                int rr = i >> 4, c4 = i & 15;
                cp16(&Ks[nxt][rr*AQ_STRIDE + c4*4], kn + (size_t)rr * DM + c4 * 4);
                cp16(&Vs[nxt][rr*AV_STRIDE + c4*4], vn + (size_t)rr * DM + c4 * 4);
            }
        }
        CP_COMMIT();

        const uint32_t* ks = (const uint32_t*)Ks[cur];
        const uint32_t* vs = (const uint32_t*)Vs[cur];

        // ---- S = Q @ K^T ----
        float sacc[8][4];
#pragma unroll
        for (int i = 0; i < 8; i++)
#pragma unroll
            for (int c = 0; c < 4; c++) sacc[i][c] = 0.f;

#pragma unroll
        for (int kf = 0; kf < 8; kf++) {
#pragma unroll
            for (int nf = 0; nf < 8; nf++) {
                uint32_t b0 = ks[(nf*8 + g)*AQ_STRIDE + kf*8 + tq];
                uint32_t b1 = ks[(nf*8 + g)*AQ_STRIDE + kf*8 + tq + 4];
                mma8(sacc[nf][0], sacc[nf][1], sacc[nf][2], sacc[nf][3],
                     qa[kf][0], qa[kf][1], qa[kf][2], qa[kf][3], b0, b1);
            }
        }

        // ---- online softmax ----
        float mx0 = -1e30f, mx1 = -1e30f;
#pragma unroll
        for (int nf = 0; nf < 8; nf++) {
            mx0 = fmaxf(mx0, fmaxf(sacc[nf][0], sacc[nf][1]));
            mx1 = fmaxf(mx1, fmaxf(sacc[nf][2], sacc[nf][3]));
        }
        mx0 = fmaxf(mx0, __shfl_xor_sync(0xffffffffu, mx0, 1));
        mx0 = fmaxf(mx0, __shfl_xor_sync(0xffffffffu, mx0, 2));
        mx1 = fmaxf(mx1, __shfl_xor_sync(0xffffffffu, mx1, 1));
        mx1 = fmaxf(mx1, __shfl_xor_sync(0xffffffffu, mx1, 2));
        float mn0 = fmaxf(m0, mx0), mn1 = fmaxf(m1, mx1);
        float al0 = __expf(m0 - mn0), al1 = __expf(m1 - mn1);

        __syncwarp();

        float sum0 = 0.f, sum1 = 0.f;
#pragma unroll
        for (int nf = 0; nf < 8; nf++) {
            float p0 = tf32f(__expf(sacc[nf][0] - mn0));
            float p1 = tf32f(__expf(sacc[nf][1] - mn0));
            float p2 = tf32f(__expf(sacc[nf][2] - mn1));
            float p3 = tf32f(__expf(sacc[nf][3] - mn1));
            sum0 += p0 + p1;
            sum1 += p2 + p3;
            *(float2*)(&Ps[(wq + g)    *AQ_STRIDE + nf*8 + 2*tq]) = make_float2(p0, p1);
            *(float2*)(&Ps[(wq + g + 8)*AQ_STRIDE + nf*8 + 2*tq]) = make_float2(p2, p3);
        }
        sum0 += __shfl_xor_sync(0xffffffffu, sum0, 1);
        sum0 += __shfl_xor_sync(0xffffffffu, sum0, 2);
        sum1 += __shfl_xor_sync(0xffffffffu, sum1, 1);
        sum1 += __shfl_xor_sync(0xffffffffu, sum1, 2);
        l0 = l0 * al0 + sum0;
        l1 = l1 * al1 + sum1;
        m0 = mn0; m1 = mn1;
#pragma unroll
        for (int nf = 0; nf < 8; nf++) {
            oacc[nf][0] *= al0; oacc[nf][1] *= al0;
            oacc[nf][2] *= al1; oacc[nf][3] *= al1;
        }
        __syncwarp();

        // ---- O += P @ V ----
        const uint32_t* psu = (const uint32_t*)Ps;
#pragma unroll
        for (int kf = 0; kf < 8; kf++) {
            uint32_t a0 = psu[(wq + g)    *AQ_STRIDE + kf*8 + tq];
            uint32_t a1 = psu[(wq + g + 8)*AQ_STRIDE + kf*8 + tq];
            uint32_t a2 = psu[(wq + g)    *AQ_STRIDE + kf*8 + tq + 4];
            uint32_t a3 = psu[(wq + g + 8)*AQ_STRIDE + kf*8 + tq + 4];
#pragma unroll
            for (int nf = 0; nf < 8; nf++) {
                uint32_t b0 = vs[(kf*8 + tq)    *AV_STRIDE + nf*8 + g];
                uint32_t b1 = vs[(kf*8 + tq + 4)*AV_STRIDE + nf*8 + g];
                mma8(oacc[nf][0], oacc[nf][1], oacc[nf][2], oacc[nf][3],
                     a0, a1, a2, a3, b0, b1);
            }
        }

        CP_WAIT0();
        __syncthreads();
    }

    float inv0 = 1.f / l0, inv1 = 1.f / l1;
    size_t row0 = (size_t)b * LL + qt * 64 + wq + g;
    size_t row1 = row0 + 8;
#pragma unroll
    for (int nf = 0; nf < 8; nf++) {
        int cN = h * HD + nf*8 + 2*tq;
        *(float2*)(o + row0 * DM + cN) =
            make_float2(tf32f(oacc[nf][0] * inv0), tf32f(oacc[nf][1] * inv0));
        *(float2*)(o + row1 * DM + cN) =
            make_float2(tf32f(oacc[nf][2] * inv1), tf32f(oacc[nf][3] * inv1));
    }
}

// ---------------- launcher ----------------
extern "C" void kernel_launch(void* const* d_in, const int* in_sizes, int n_in,
                              void* d_out, int out_size)
{
    const float* x     = (const float*)d_in[0];
    const float* Wq    = (const float*)d_in[1];
    const float* bq    = (const float*)d_in[2];
    const float* Wk    = (const float*)d_in[3];
    const float* bk    = (const float*)d_in[4];
    const float* Wv    = (const float*)d_in[5];
    const float* bv    = (const float*)d_in[6];
    const float* Wo    = (const float*)d_in[7];
    const float* bo    = (const float*)d_in[8];
    const float* ln1_g = (const float*)d_in[9];
    const float* ln1_b = (const float*)d_in[10];
    const float* ln2_g = (const float*)d_in[11];
    const float* ln2_b = (const float*)d_in[12];
    const float* W1    = (const float*)d_in[13];
    const float* b1    = (const float*)d_in[14];
    const float* W2    = (const float*)d_in[15];
    const float* b2    = (const float*)d_in[16];
    float* out = (float*)d_out;

    float *xn, *q, *k, *v, *o, *x2, *xn2, *hb;
    float *xr, *wq, *wk, *wv, *wo, *w1, *w2;
    cudaGetSymbolAddress((void**)&xn,  g_xn);
    cudaGetSymbolAddress((void**)&q,   g_q);
    cudaGetSymbolAddress((void**)&k,   g_k);
    cudaGetSymbolAddress((void**)&v,   g_v);
    cudaGetSymbolAddress((void**)&o,   g_o);
    cudaGetSymbolAddress((void**)&x2,  g_x2);
    cudaGetSymbolAddress((void**)&xn2, g_xn2);
    cudaGetSymbolAddress((void**)&hb,  g_h);
    cudaGetSymbolAddress((void**)&xr,  g_xr);
    cudaGetSymbolAddress((void**)&wq,  g_wq);
    cudaGetSymbolAddress((void**)&wk,  g_wk);
    cudaGetSymbolAddress((void**)&wv,  g_wv);
    cudaGetSymbolAddress((void**)&wo,  g_wo);
    cudaGetSymbolAddress((void**)&w1,  g_w1);
    cudaGetSymbolAddress((void**)&w2,  g_w2);

    static bool attr_set = false;
    if (!attr_set) {
        cudaFuncSetAttribute((const void*)tgemm<false,false,true>,  cudaFuncAttributeMaxDynamicSharedMemorySize, GEMM_SMEM);
        cudaFuncSetAttribute((const void*)tgemm<false,true,false>,  cudaFuncAttributeMaxDynamicSharedMemorySize, GEMM_SMEM);
        cudaFuncSetAttribute((const void*)tgemm<true,false,true>,   cudaFuncAttributeMaxDynamicSharedMemorySize, GEMM_SMEM);
        cudaFuncSetAttribute((const void*)attn_kernel, cudaFuncAttributeMaxDynamicSharedMemorySize, ATTN_SMEM);
        attr_set = true;
    }

    // round external operands to tf32-representable fp32
    round_tf32_kernel<<<(NTOK*DM/4 + 255)/256, 256>>>(x,  xr, NTOK*DM/4);
    round_tf32_kernel<<<(DM*DM/4   + 255)/256, 256>>>(Wq, wq, DM*DM/4);
    round_tf32_kernel<<<(DM*DM/4   + 255)/256, 256>>>(Wk, wk, DM*DM/4);
    round_tf32_kernel<<<(DM*DM/4   + 255)/256, 256>>>(Wv, wv, DM*DM/4);
    round_tf32_kernel<<<(DM*DM/4   + 255)/256, 256>>>(Wo, wo, DM*DM/4);
    round_tf32_kernel<<<(DM*DFF/4  + 255)/256, 256>>>(W1, w1, DM*DFF/4);
    round_tf32_kernel<<<(DFF*DM/4  + 255)/256, 256>>>(W2, w2, DFF*DM/4);

    ln_kernel<<<NTOK, 256>>>(x, ln1_g, ln1_b, xn);   // rounded output

    dim3 g1(DM / 128, NTOK / 128);
    tgemm<false,false,true><<<g1, 256, GEMM_SMEM>>>(xn, wq, bq, nullptr, q, NTOK, DM, DM);
    tgemm<false,false,true><<<g1, 256, GEMM_SMEM>>>(xr, wk, bk, nullptr, k, NTOK, DM, DM);
    tgemm<false,false,true><<<g1, 256, GEMM_SMEM>>>(xr, wv, bv, nullptr, v, NTOK, DM, DM);

    const int pairs = NTOK * NH * (HD / 2);
    rope_kernel<<<(pairs + 255) / 256, 256>>>(q, k);

    dim3 ga(LL / 64, NH, BB);
    attn_kernel<<<ga, 128, ATTN_SMEM>>>(q, k, v, o);

    // O projection + residual (res = original fp32 x), full-precision output
    tgemm<false,true,false><<<g1, 256, GEMM_SMEM>>>(o, wo, bo, x, x2, NTOK, DM, DM);

    ln_kernel<<<NTOK, 256>>>(x2, ln2_g, ln2_b, xn2); // rounded output

    dim3 g2(DFF / 128, NTOK / 128);
    tgemm<true,false,true><<<g2, 256, GEMM_SMEM>>>(xn2, w1, b1, nullptr, hb, NTOK, DFF, DM);
    tgemm<false,true,false><<<g1, 256, GEMM_SMEM>>>(hb, w2, b2, x2, out, NTOK, DM, DFF);
}

// round 6
// speedup vs baseline: 9.4645x; 1.1035x over previous
#include <cuda_runtime.h>
#include <math.h>
#include <stdint.h>

#define BB 2
#define LL 2048
#define DM 1024
#define NH 16
#define HD 64
#define DFF 4096
#define NTOK (BB*LL)
#define LN_EPS 1e-5f

// ---------------- scratch (no allocation allowed) ----------------
__device__ float g_xn [NTOK*DM];
__device__ float g_q  [NTOK*DM];
__device__ float g_k  [NTOK*DM];
__device__ float g_v  [NTOK*DM];
__device__ float g_o  [NTOK*DM];
__device__ float g_x2 [NTOK*DM];
__device__ float g_xn2[NTOK*DM];
__device__ float g_h  [NTOK*DFF];
// tf32-rounded copies of external operands
__device__ float g_xr [NTOK*DM];
__device__ float g_wq [DM*DM];
__device__ float g_wk [DM*DM];
__device__ float g_wv [DM*DM];
__device__ float g_wo [DM*DM];
__device__ float g_w1 [DM*DFF];
__device__ float g_w2 [DFF*DM];

// ---------------- helpers ----------------
__device__ __forceinline__ void cp16(void* smem, const void* g) {
    unsigned sa = (unsigned)__cvta_generic_to_shared(smem);
    asm volatile("cp.async.cg.shared.global [%0], [%1], 16;" :: "r"(sa), "l"(g));
}
#define CP_COMMIT() asm volatile("cp.async.commit_group;" ::: "memory")
#define CP_WAIT0()  asm volatile("cp.async.wait_group 0;" ::: "memory")
#define CP_WAIT1()  asm volatile("cp.async.wait_group 1;" ::: "memory")

__device__ __forceinline__ uint32_t to_tf32(float x) {
    uint32_t r;
    asm("cvt.rna.tf32.f32 %0, %1;" : "=r"(r) : "f"(x));
    return r;
}
__device__ __forceinline__ float tf32f(float x) {
    return __uint_as_float(to_tf32(x));
}
__device__ __forceinline__ void mma8(float& c0, float& c1, float& c2, float& c3,
                                     uint32_t a0, uint32_t a1, uint32_t a2, uint32_t a3,
                                     uint32_t b0, uint32_t b1) {
    asm("mma.sync.aligned.m16n8k8.row.col.f32.tf32.tf32.f32 "
        "{%0,%1,%2,%3},{%4,%5,%6,%7},{%8,%9},{%0,%1,%2,%3};"
        : "+f"(c0), "+f"(c1), "+f"(c2), "+f"(c3)
        : "r"(a0), "r"(a1), "r"(a2), "r"(a3), "r"(b0), "r"(b1));
}

// ---------------- tf32 rounding pass ----------------
__global__ void round_tf32_kernel(const float* __restrict__ in, float* __restrict__ out, int n4)
{
    int i = blockIdx.x * blockDim.x + threadIdx.x;
    if (i >= n4) return;
    float4 v = ((const float4*)in)[i];
    v.x = tf32f(v.x); v.y = tf32f(v.y); v.z = tf32f(v.z); v.w = tf32f(v.w);
    ((float4*)out)[i] = v;
}

// ---------------- LayerNorm (output rounded to tf32) ----------------
__global__ void ln_kernel(const float* __restrict__ x, const float* __restrict__ g,
                          const float* __restrict__ b, float* __restrict__ y)
{
    int row = blockIdx.x;
    int t = threadIdx.x;
    const float4* xr = (const float4*)(x + (size_t)row * DM);
    float4 v = xr[t];
    float s  = v.x + v.y + v.z + v.w;
    float ss = v.x*v.x + v.y*v.y + v.z*v.z + v.w*v.w;
#pragma unroll
    for (int o = 16; o; o >>= 1) {
        s  += __shfl_xor_sync(0xffffffffu, s,  o);
        ss += __shfl_xor_sync(0xffffffffu, ss, o);
    }
    __shared__ float sh_s[8], sh_ss[8];
    int w = t >> 5, lane = t & 31;
    if (lane == 0) { sh_s[w] = s; sh_ss[w] = ss; }
    __syncthreads();
    if (t < 32) {
        s  = (t < 8) ? sh_s[t]  : 0.f;
        ss = (t < 8) ? sh_ss[t] : 0.f;
#pragma unroll
        for (int o = 4; o; o >>= 1) {
            s  += __shfl_xor_sync(0xffffffffu, s,  o);
            ss += __shfl_xor_sync(0xffffffffu, ss, o);
        }
        if (t == 0) { sh_s[0] = s; sh_ss[0] = ss; }
    }
    __syncthreads();
    float mu  = sh_s[0] * (1.f / DM);
    float var = sh_ss[0] * (1.f / DM) - mu * mu;
    float inv = rsqrtf(var + LN_EPS);
    float4 gv = ((const float4*)g)[t];
    float4 bv = ((const float4*)b)[t];
    float4 o4;
    o4.x = tf32f((v.x - mu) * inv * gv.x + bv.x);
    o4.y = tf32f((v.y - mu) * inv * gv.y + bv.y);
    o4.z = tf32f((v.z - mu) * inv * gv.z + bv.z);
    o4.w = tf32f((v.w - mu) * inv * gv.w + bv.w);
    ((float4*)(y + (size_t)row * DM))[t] = o4;
}

// ---------------- RoPE (heads < 8) + q scale, tf32-rounded out ----------------
__global__ void rope_kernel(float* __restrict__ q, float* __restrict__ k)
{
    int idx = blockIdx.x * blockDim.x + threadIdx.x;
    const int total = NTOK * NH * (HD / 2);
    if (idx >= total) return;
    int i   = idx & 31;
    int h   = (idx >> 5) & 15;
    int tok = idx >> 9;
    int l   = tok & (LL - 1);
    size_t base = (size_t)tok * DM + h * HD + 2 * i;

    float q1 = q[base], q2 = q[base + 1];
    if (h < 8) {
        double invf = pow(10000.0, -(double)i / 32.0);
        double ang = (double)l * invf;
        float cs = (float)cos(ang);
        float sn = (float)sin(ang);
        float qe = q1 * cs - q2 * sn;
        float qo = q1 * sn + q2 * cs;
        q1 = qe; q2 = qo;
        float k1 = k[base], k2 = k[base + 1];
        k[base]     = tf32f(k1 * cs - k2 * sn);
        k[base + 1] = tf32f(k1 * sn + k2 * cs);
    }
    q[base]     = tf32f(q1 * 0.125f);
    q[base + 1] = tf32f(q2 * 0.125f);
}

// ---------------- tf32 tensor-core GEMM v3 ----------------
// C[M,N] = A[M,K] @ B[K,N] + bias (+res) (relu) (round)
// 128x128 block tile, 128 threads = 4 warps (2m x 2n), warp tile 64x64.
// BK=32, 3-stage cp.async ring. As: [128][36], Bs: [32][136].
#define GA_STRIDE 36
#define GB_STRIDE 136
#define GA_FLOATS (128*GA_STRIDE)   // 4608
#define GB_FLOATS (32*GB_STRIDE)    // 4352
#define STAGE_FLOATS (GA_FLOATS + GB_FLOATS)   // 8960
#define GEMM_SMEM (3*STAGE_FLOATS*4)           // 107520 bytes

template<bool RELU, bool RES, bool ROUND>
__global__ __launch_bounds__(128, 2)
void tgemm(const float* __restrict__ A, const float* __restrict__ Bm,
           const float* __restrict__ bias, const float* __restrict__ res,
           float* __restrict__ C, int M, int N, int K)
{
    extern __shared__ float dsm[];
    int t = threadIdx.x;
    int wid = t >> 5, lane = t & 31;
    int g = lane >> 2, tq = lane & 3;
    int m0 = blockIdx.y * 128, n0 = blockIdx.x * 128;
    int wm = (wid >> 1) * 64;     // 0 or 64
    int wn = (wid & 1) * 64;      // 0 or 64

    float acc[4][8][4];
#pragma unroll
    for (int i = 0; i < 4; i++)
#pragma unroll
        for (int j = 0; j < 8; j++)
#pragma unroll
            for (int c = 0; c < 4; c++) acc[i][j][c] = 0.f;

    const int NK = K >> 5;

    // prologue: stages 0,1
#pragma unroll
    for (int s = 0; s < 2; s++) {
        float* as = dsm + s * STAGE_FLOATS;
        float* bs = as + GA_FLOATS;
        int kb = s << 5;
#pragma unroll
        for (int u = 0; u < 8; u++) {
            int i = t + u * 128;
            int row = i >> 3, ch = i & 7;
            cp16(&as[row*GA_STRIDE + ch*4], A + (size_t)(m0 + row) * K + kb + ch * 4);
        }
#pragma unroll
        for (int u = 0; u < 8; u++) {
            int i = t + u * 128;
            int row = i >> 5, c4 = i & 31;
            cp16(&bs[row*GB_STRIDE + c4*4], Bm + (size_t)(kb + row) * N + n0 + c4 * 4);
        }
        CP_COMMIT();
    }

    for (int j = 0; j < NK; j++) {
        if (j + 2 < NK) { CP_WAIT1(); } else { CP_WAIT0(); }
        __syncthreads();

        int buf = j % 3;
        const uint32_t* as = (const uint32_t*)(dsm + buf * STAGE_FLOATS);
        const uint32_t* bs = as + GA_FLOATS;

#pragma unroll
        for (int kf = 0; kf < 4; kf++) {
            uint32_t bf[8][2];
#pragma unroll
            for (int nf = 0; nf < 8; nf++) {
                bf[nf][0] = bs[(kf*8 + tq)    *GB_STRIDE + wn + nf*8 + g];
                bf[nf][1] = bs[(kf*8 + tq + 4)*GB_STRIDE + wn + nf*8 + g];
            }
#pragma unroll
            for (int mf = 0; mf < 4; mf++) {
                int row = wm + mf * 16;
                uint32_t a0 = as[(row + g)    *GA_STRIDE + kf*8 + tq];
                uint32_t a1 = as[(row + g + 8)*GA_STRIDE + kf*8 + tq];
                uint32_t a2 = as[(row + g)    *GA_STRIDE + kf*8 + tq + 4];
                uint32_t a3 = as[(row + g + 8)*GA_STRIDE + kf*8 + tq + 4];
#pragma unroll
                for (int nf = 0; nf < 8; nf++)
                    mma8(acc[mf][nf][0], acc[mf][nf][1], acc[mf][nf][2], acc[mf][nf][3],
                         a0, a1, a2, a3, bf[nf][0], bf[nf][1]);
            }
        }

        if (j + 2 < NK) {
            int s = (j + 2) % 3;
            float* asw = dsm + s * STAGE_FLOATS;
            float* bsw = asw + GA_FLOATS;
            int kb = (j + 2) << 5;
#pragma unroll
            for (int u = 0; u < 8; u++) {
                int i = t + u * 128;
                int row = i >> 3, ch = i & 7;
                cp16(&asw[row*GA_STRIDE + ch*4], A + (size_t)(m0 + row) * K + kb + ch * 4);
            }
#pragma unroll
            for (int u = 0; u < 8; u++) {
                int i = t + u * 128;
                int row = i >> 5, c4 = i & 31;
                cp16(&bsw[row*GB_STRIDE + c4*4], Bm + (size_t)(kb + row) * N + n0 + c4 * 4);
            }
            CP_COMMIT();
        }
    }

    // epilogue
#pragma unroll
    for (int mf = 0; mf < 4; mf++) {
#pragma unroll
        for (int nf = 0; nf < 8; nf++) {
            int r0 = m0 + wm + mf*16 + g;
            int r1 = r0 + 8;
            int cN = n0 + wn + nf*8 + 2*tq;
            float b0v = bias[cN], b1v = bias[cN + 1];
            float v0 = acc[mf][nf][0] + b0v;
            float v1 = acc[mf][nf][1] + b1v;
            float v2 = acc[mf][nf][2] + b0v;
            float v3 = acc[mf][nf][3] + b1v;
            if (RES) {
                v0 += res[(size_t)r0 * N + cN];     v1 += res[(size_t)r0 * N + cN + 1];
                v2 += res[(size_t)r1 * N + cN];     v3 += res[(size_t)r1 * N + cN + 1];
            }
            if (RELU) {
                v0 = fmaxf(v0, 0.f); v1 = fmaxf(v1, 0.f);
                v2 = fmaxf(v2, 0.f); v3 = fmaxf(v3, 0.f);
            }
            if (ROUND) {
                v0 = tf32f(v0); v1 = tf32f(v1); v2 = tf32f(v2); v3 = tf32f(v3);
            }
            *(float2*)(C + (size_t)r0 * N + cN) = make_float2(v0, v1);
            *(float2*)(C + (size_t)r1 * N + cN) = make_float2(v2, v3);
        }
    }
}

// ---------------- tf32 flash attention (R4, unchanged) ----------------
#define AQ_STRIDE 68
#define AV_STRIDE 72
#define AQ_FLOATS (64*AQ_STRIDE)
#define AV_FLOATS (64*AV_STRIDE)
#define ATTN_SMEM ((AQ_FLOATS + 2*AQ_FLOATS + 2*AV_FLOATS + AQ_FLOATS)*4)

__global__ __launch_bounds__(128, 2)
void attn_kernel(const float* __restrict__ q, const float* __restrict__ k,
                 const float* __restrict__ v, float* __restrict__ o)
{
    extern __shared__ float sm[];
    float* Qs = sm;
    float* Ks[2] = { sm + AQ_FLOATS, sm + 2*AQ_FLOATS };
    float* Vs[2] = { sm + 3*AQ_FLOATS, sm + 3*AQ_FLOATS + AV_FLOATS };
    float* Ps = sm + 3*AQ_FLOATS + 2*AV_FLOATS;

    int qt = blockIdx.x, h = blockIdx.y, b = blockIdx.z;
    int t = threadIdx.x;
    int wid = t >> 5, lane = t & 31;
    int g = lane >> 2, tq = lane & 3;
    int wq = wid * 16;

    const float* qbh = q + ((size_t)b * LL + qt * 64) * DM + h * HD;
    const float* kbh = k + (size_t)b * LL * DM + h * HD;
    const float* vbh = v + (size_t)b * LL * DM + h * HD;

#pragma unroll
    for (int u = 0; u < 8; u++) {
        int i = t + u * 128;
        int rr = i >> 4, c4 = i & 15;
        cp16(&Qs[rr*AQ_STRIDE + c4*4], qbh + (size_t)rr * DM + c4 * 4);
    }
#pragma unroll
    for (int u = 0; u < 8; u++) {
        int i = t + u * 128;
        int rr = i >> 4, c4 = i & 15;
        cp16(&Ks[0][rr*AQ_STRIDE + c4*4], kbh + (size_t)rr * DM + c4 * 4);
        cp16(&Vs[0][rr*AV_STRIDE + c4*4], vbh + (size_t)rr * DM + c4 * 4);
    }
    CP_COMMIT(); CP_WAIT0(); __syncthreads();

    uint32_t qa[8][4];
    {
        const uint32_t* qsu = (const uint32_t*)Qs;
#pragma unroll
        for (int kf = 0; kf < 8; kf++) {
            qa[kf][0] = qsu[(wq + g)    *AQ_STRIDE + kf*8 + tq];
            qa[kf][1] = qsu[(wq + g + 8)*AQ_STRIDE + kf*8 + tq];
            qa[kf][2] = qsu[(wq + g)    *AQ_STRIDE + kf*8 + tq + 4];
            qa[kf][3] = qsu[(wq + g + 8)*AQ_STRIDE + kf*8 + tq + 4];
        }
    }

    float oacc[8][4];
#pragma unroll
    for (int i = 0; i < 8; i++)
#pragma unroll
        for (int c = 0; c < 4; c++) oacc[i][c] = 0.f;
    float m0 = -1e30f, m1 = -1e30f, l0 = 0.f, l1 = 0.f;

    for (int j = 0; j < LL/64; j++) {
        int cur = j & 1;
        if (j + 1 < LL/64) {
            int nxt = cur ^ 1;
            const float* kn = kbh + (size_t)(j + 1) * 64 * DM;
            const float* vn = vbh + (size_t)(j + 1) * 64 * DM;
#pragma unroll
            for (int u = 0; u < 8; u++) {
                int i = t + u * 128;
                int rr = i >> 4, c4 = i & 15;
                cp16(&Ks[nxt][rr*AQ_STRIDE + c4*4], kn + (size_t)rr * DM + c4 * 4);
                cp16(&Vs[nxt][rr*AV_STRIDE + c4*4], vn + (size_t)rr * DM + c4 * 4);
            }
        }
        CP_COMMIT();

        const uint32_t* ks = (const uint32_t*)Ks[cur];
        const uint32_t* vs = (const uint32_t*)Vs[cur];

        float sacc[8][4];
#pragma unroll
        for (int i = 0; i < 8; i++)
#pragma unroll
            for (int c = 0; c < 4; c++) sacc[i][c] = 0.f;

#pragma unroll
        for (int kf = 0; kf < 8; kf++) {
#pragma unroll
            for (int nf = 0; nf < 8; nf++) {
                uint32_t b0 = ks[(nf*8 + g)*AQ_STRIDE + kf*8 + tq];
                uint32_t b1 = ks[(nf*8 + g)*AQ_STRIDE + kf*8 + tq + 4];
                mma8(sacc[nf][0], sacc[nf][1], sacc[nf][2], sacc[nf][3],
                     qa[kf][0], qa[kf][1], qa[kf][2], qa[kf][3], b0, b1);
            }
        }

        float mx0 = -1e30f, mx1 = -1e30f;
#pragma unroll
        for (int nf = 0; nf < 8; nf++) {
            mx0 = fmaxf(mx0, fmaxf(sacc[nf][0], sacc[nf][1]));
            mx1 = fmaxf(mx1, fmaxf(sacc[nf][2], sacc[nf][3]));
        }
        mx0 = fmaxf(mx0, __shfl_xor_sync(0xffffffffu, mx0, 1));
        mx0 = fmaxf(mx0, __shfl_xor_sync(0xffffffffu, mx0, 2));
        mx1 = fmaxf(mx1, __shfl_xor_sync(0xffffffffu, mx1, 1));
        mx1 = fmaxf(mx1, __shfl_xor_sync(0xffffffffu, mx1, 2));
        float mn0 = fmaxf(m0, mx0), mn1 = fmaxf(m1, mx1);
        float al0 = __expf(m0 - mn0), al1 = __expf(m1 - mn1);

        __syncwarp();

        float sum0 = 0.f, sum1 = 0.f;
#pragma unroll
        for (int nf = 0; nf < 8; nf++) {
            float p0 = tf32f(__expf(sacc[nf][0] - mn0));
            float p1 = tf32f(__expf(sacc[nf][1] - mn0));
            float p2 = tf32f(__expf(sacc[nf][2] - mn1));
            float p3 = tf32f(__expf(sacc[nf][3] - mn1));
            sum0 += p0 + p1;
            sum1 += p2 + p3;
            *(float2*)(&Ps[(wq + g)    *AQ_STRIDE + nf*8 + 2*tq]) = make_float2(p0, p1);
            *(float2*)(&Ps[(wq + g + 8)*AQ_STRIDE + nf*8 + 2*tq]) = make_float2(p2, p3);
        }
        sum0 += __shfl_xor_sync(0xffffffffu, sum0, 1);
        sum0 += __shfl_xor_sync(0xffffffffu, sum0, 2);
        sum1 += __shfl_xor_sync(0xffffffffu, sum1, 1);
        sum1 += __shfl_xor_sync(0xffffffffu, sum1, 2);
        l0 = l0 * al0 + sum0;
        l1 = l1 * al1 + sum1;
        m0 = mn0; m1 = mn1;
#pragma unroll
        for (int nf = 0; nf < 8; nf++) {
            oacc[nf][0] *= al0; oacc[nf][1] *= al0;
            oacc[nf][2] *= al1; oacc[nf][3] *= al1;
        }
        __syncwarp();

        const uint32_t* psu = (const uint32_t*)Ps;
#pragma unroll
        for (int kf = 0; kf < 8; kf++) {
            uint32_t a0 = psu[(wq + g)    *AQ_STRIDE + kf*8 + tq];
            uint32_t a1 = psu[(wq + g + 8)*AQ_STRIDE + kf*8 + tq];
            uint32_t a2 = psu[(wq + g)    *AQ_STRIDE + kf*8 + tq + 4];
            uint32_t a3 = psu[(wq + g + 8)*AQ_STRIDE + kf*8 + tq + 4];
#pragma unroll
            for (int nf = 0; nf < 8; nf++) {
                uint32_t b0 = vs[(kf*8 + tq)    *AV_STRIDE + nf*8 + g];
                uint32_t b1 = vs[(kf*8 + tq + 4)*AV_STRIDE + nf*8 + g];
                mma8(oacc[nf][0], oacc[nf][1], oacc[nf][2], oacc[nf][3],
                     a0, a1, a2, a3, b0, b1);
            }
        }

        CP_WAIT0();
        __syncthreads();
    }

    float inv0 = 1.f / l0, inv1 = 1.f / l1;
    size_t row0 = (size_t)b * LL + qt * 64 + wq + g;
    size_t row1 = row0 + 8;
#pragma unroll
    for (int nf = 0; nf < 8; nf++) {
        int cN = h * HD + nf*8 + 2*tq;
        *(float2*)(o + row0 * DM + cN) =
            make_float2(tf32f(oacc[nf][0] * inv0), tf32f(oacc[nf][1] * inv0));
        *(float2*)(o + row1 * DM + cN) =
            make_float2(tf32f(oacc[nf][2] * inv1), tf32f(oacc[nf][3] * inv1));
    }
}

// ---------------- launcher ----------------
extern "C" void kernel_launch(void* const* d_in, const int* in_sizes, int n_in,
                              void* d_out, int out_size)
{
    const float* x     = (const float*)d_in[0];
    const float* Wq    = (const float*)d_in[1];
    const float* bq    = (const float*)d_in[2];
    const float* Wk    = (const float*)d_in[3];
    const float* bk    = (const float*)d_in[4];
    const float* Wv    = (const float*)d_in[5];
    const float* bv    = (const float*)d_in[6];
    const float* Wo    = (const float*)d_in[7];
    const float* bo    = (const float*)d_in[8];
    const float* ln1_g = (const float*)d_in[9];
    const float* ln1_b = (const float*)d_in[10];
    const float* ln2_g = (const float*)d_in[11];
    const float* ln2_b = (const float*)d_in[12];
    const float* W1    = (const float*)d_in[13];
    const float* b1    = (const float*)d_in[14];
    const float* W2    = (const float*)d_in[15];
    const float* b2    = (const float*)d_in[16];
    float* out = (float*)d_out;

    float *xn, *q, *k, *v, *o, *x2, *xn2, *hb;
    float *xr, *wq, *wk, *wv, *wo, *w1, *w2;
    cudaGetSymbolAddress((void**)&xn,  g_xn);
    cudaGetSymbolAddress((void**)&q,   g_q);
    cudaGetSymbolAddress((void**)&k,   g_k);
    cudaGetSymbolAddress((void**)&v,   g_v);
    cudaGetSymbolAddress((void**)&o,   g_o);
    cudaGetSymbolAddress((void**)&x2,  g_x2);
    cudaGetSymbolAddress((void**)&xn2, g_xn2);
    cudaGetSymbolAddress((void**)&hb,  g_h);
    cudaGetSymbolAddress((void**)&xr,  g_xr);
    cudaGetSymbolAddress((void**)&wq,  g_wq);
    cudaGetSymbolAddress((void**)&wk,  g_wk);
    cudaGetSymbolAddress((void**)&wv,  g_wv);
    cudaGetSymbolAddress((void**)&wo,  g_wo);
    cudaGetSymbolAddress((void**)&w1,  g_w1);
    cudaGetSymbolAddress((void**)&w2,  g_w2);

    static bool attr_set = false;
    if (!attr_set) {
        cudaFuncSetAttribute((const void*)tgemm<false,false,true>, cudaFuncAttributeMaxDynamicSharedMemorySize, GEMM_SMEM);
        cudaFuncSetAttribute((const void*)tgemm<false,true,false>, cudaFuncAttributeMaxDynamicSharedMemorySize, GEMM_SMEM);
        cudaFuncSetAttribute((const void*)tgemm<true,false,true>,  cudaFuncAttributeMaxDynamicSharedMemorySize, GEMM_SMEM);
        cudaFuncSetAttribute((const void*)attn_kernel, cudaFuncAttributeMaxDynamicSharedMemorySize, ATTN_SMEM);
        attr_set = true;
    }

    // round external operands to tf32-representable fp32
    round_tf32_kernel<<<(NTOK*DM/4 + 255)/256, 256>>>(x,  xr, NTOK*DM/4);
    round_tf32_kernel<<<(DM*DM/4   + 255)/256, 256>>>(Wq, wq, DM*DM/4);
    round_tf32_kernel<<<(DM*DM/4   + 255)/256, 256>>>(Wk, wk, DM*DM/4);
    round_tf32_kernel<<<(DM*DM/4   + 255)/256, 256>>>(Wv, wv, DM*DM/4);
    round_tf32_kernel<<<(DM*DM/4   + 255)/256, 256>>>(Wo, wo, DM*DM/4);
    round_tf32_kernel<<<(DM*DFF/4  + 255)/256, 256>>>(W1, w1, DM*DFF/4);
    round_tf32_kernel<<<(DFF*DM/4  + 255)/256, 256>>>(W2, w2, DFF*DM/4);

    ln_kernel<<<NTOK, 256>>>(x, ln1_g, ln1_b, xn);

    dim3 g1(DM / 128, NTOK / 128);     // (8, 32)
    tgemm<false,false,true><<<g1, 128, GEMM_SMEM>>>(xn, wq, bq, nullptr, q, NTOK, DM, DM);
    tgemm<false,false,true><<<g1, 128, GEMM_SMEM>>>(xr, wk, bk, nullptr, k, NTOK, DM, DM);
    tgemm<false,false,true><<<g1, 128, GEMM_SMEM>>>(xr, wv, bv, nullptr, v, NTOK, DM, DM);

    const int pairs = NTOK * NH * (HD / 2);
    rope_kernel<<<(pairs + 255) / 256, 256>>>(q, k);

    dim3 ga(LL / 64, NH, BB);
    attn_kernel<<<ga, 128, ATTN_SMEM>>>(q, k, v, o);

    tgemm<false,true,false><<<g1, 128, GEMM_SMEM>>>(o, wo, bo, x, x2, NTOK, DM, DM);

    ln_kernel<<<NTOK, 256>>>(x2, ln2_g, ln2_b, xn2);

    dim3 g2(DFF / 128, NTOK / 128);    // (32, 32)
    tgemm<true,false,true><<<g2, 128, GEMM_SMEM>>>(xn2, w1, b1, nullptr, hb, NTOK, DFF, DM);
    tgemm<false,true,false><<<g1, 128, GEMM_SMEM>>>(hb, w2, b2, x2, out, NTOK, DM, DFF);
}

// round 7
// speedup vs baseline: 11.3564x; 1.1999x over previous
#include <cuda_runtime.h>
#include <cuda_fp16.h>
#include <math.h>
#include <stdint.h>

#define BB 2
#define LL 2048
#define DM 1024
#define NH 16
#define HD 64
#define DFF 4096
#define NTOK (BB*LL)
#define LN_EPS 1e-5f

// ---------------- scratch (no allocation allowed) ----------------
__device__ float g_xn [NTOK*DM];
__device__ float g_q  [NTOK*DM];
__device__ float g_k  [NTOK*DM];
__device__ float g_v  [NTOK*DM];
__device__ float g_o  [NTOK*DM];
__device__ float g_x2 [NTOK*DM];
__device__ float g_xn2[NTOK*DM];
__device__ float g_h  [NTOK*DFF];
__device__ __half g_qh[NTOK*DM];
__device__ __half g_kh[NTOK*DM];
__device__ __half g_vh[NTOK*DM];
// tf32-rounded copies of external operands
__device__ float g_xr [NTOK*DM];
__device__ float g_wq [DM*DM];
__device__ float g_wk [DM*DM];
__device__ float g_wv [DM*DM];
__device__ float g_wo [DM*DM];
__device__ float g_w1 [DM*DFF];
__device__ float g_w2 [DFF*DM];

// ---------------- helpers ----------------
__device__ __forceinline__ void cp16(void* smem, const void* g) {
    unsigned sa = (unsigned)__cvta_generic_to_shared(smem);
    asm volatile("cp.async.cg.shared.global [%0], [%1], 16;" :: "r"(sa), "l"(g));
}
#define CP_COMMIT() asm volatile("cp.async.commit_group;" ::: "memory")
#define CP_WAIT0()  asm volatile("cp.async.wait_group 0;" ::: "memory")
#define CP_WAIT1()  asm volatile("cp.async.wait_group 1;" ::: "memory")

__device__ __forceinline__ uint32_t to_tf32(float x) {
    uint32_t r;
    asm("cvt.rna.tf32.f32 %0, %1;" : "=r"(r) : "f"(x));
    return r;
}
__device__ __forceinline__ float tf32f(float x) {
    return __uint_as_float(to_tf32(x));
}
__device__ __forceinline__ void mma8(float& c0, float& c1, float& c2, float& c3,
                                     uint32_t a0, uint32_t a1, uint32_t a2, uint32_t a3,
                                     uint32_t b0, uint32_t b1) {
    asm("mma.sync.aligned.m16n8k8.row.col.f32.tf32.tf32.f32 "
        "{%0,%1,%2,%3},{%4,%5,%6,%7},{%8,%9},{%0,%1,%2,%3};"
        : "+f"(c0), "+f"(c1), "+f"(c2), "+f"(c3)
        : "r"(a0), "r"(a1), "r"(a2), "r"(a3), "r"(b0), "r"(b1));
}
__device__ __forceinline__ void mma16(float& c0, float& c1, float& c2, float& c3,
                                      uint32_t a0, uint32_t a1, uint32_t a2, uint32_t a3,
                                      uint32_t b0, uint32_t b1) {
    asm("mma.sync.aligned.m16n8k16.row.col.f32.f16.f16.f32 "
        "{%0,%1,%2,%3},{%4,%5,%6,%7},{%8,%9},{%0,%1,%2,%3};"
        : "+f"(c0), "+f"(c1), "+f"(c2), "+f"(c3)
        : "r"(a0), "r"(a1), "r"(a2), "r"(a3), "r"(b0), "r"(b1));
}
// pack two floats to half2: lo = x, hi = y
__device__ __forceinline__ uint32_t pack_h2(float x, float y) {
    uint32_t r;
    asm("cvt.rn.f16x2.f32 %0, %1, %2;" : "=r"(r) : "f"(y), "f"(x));
    return r;
}
__device__ __forceinline__ void ldmx4t(uint32_t& r0, uint32_t& r1, uint32_t& r2, uint32_t& r3,
                                       uint32_t addr) {
    asm volatile("ldmatrix.sync.aligned.m8n8.x4.trans.shared.b16 {%0,%1,%2,%3}, [%4];"
                 : "=r"(r0), "=r"(r1), "=r"(r2), "=r"(r3) : "r"(addr));
}

// ---------------- tf32 rounding pass ----------------
__global__ void round_tf32_kernel(const float* __restrict__ in, float* __restrict__ out, int n4)
{
    int i = blockIdx.x * blockDim.x + threadIdx.x;
    if (i >= n4) return;
    float4 v = ((const float4*)in)[i];
    v.x = tf32f(v.x); v.y = tf32f(v.y); v.z = tf32f(v.z); v.w = tf32f(v.w);
    ((float4*)out)[i] = v;
}

// ---------------- LayerNorm (output rounded to tf32) ----------------
__global__ void ln_kernel(const float* __restrict__ x, const float* __restrict__ g,
                          const float* __restrict__ b, float* __restrict__ y)
{
    int row = blockIdx.x;
    int t = threadIdx.x;
    const float4* xr = (const float4*)(x + (size_t)row * DM);
    float4 v = xr[t];
    float s  = v.x + v.y + v.z + v.w;
    float ss = v.x*v.x + v.y*v.y + v.z*v.z + v.w*v.w;
#pragma unroll
    for (int o = 16; o; o >>= 1) {
        s  += __shfl_xor_sync(0xffffffffu, s,  o);
        ss += __shfl_xor_sync(0xffffffffu, ss, o);
    }
    __shared__ float sh_s[8], sh_ss[8];
    int w = t >> 5, lane = t & 31;
    if (lane == 0) { sh_s[w] = s; sh_ss[w] = ss; }
    __syncthreads();
    if (t < 32) {
        s  = (t < 8) ? sh_s[t]  : 0.f;
        ss = (t < 8) ? sh_ss[t] : 0.f;
#pragma unroll
        for (int o = 4; o; o >>= 1) {
            s  += __shfl_xor_sync(0xffffffffu, s,  o);
            ss += __shfl_xor_sync(0xffffffffu, ss, o);
        }
        if (t == 0) { sh_s[0] = s; sh_ss[0] = ss; }
    }
    __syncthreads();
    float mu  = sh_s[0] * (1.f / DM);
    float var = sh_ss[0] * (1.f / DM) - mu * mu;
    float inv = rsqrtf(var + LN_EPS);
    float4 gv = ((const float4*)g)[t];
    float4 bv = ((const float4*)b)[t];
    float4 o4;
    o4.x = tf32f((v.x - mu) * inv * gv.x + bv.x);
    o4.y = tf32f((v.y - mu) * inv * gv.y + bv.y);
    o4.z = tf32f((v.z - mu) * inv * gv.z + bv.z);
    o4.w = tf32f((v.w - mu) * inv * gv.w + bv.w);
    ((float4*)(y + (size_t)row * DM))[t] = o4;
}

// ---------------- RoPE (heads < 8) + q scale + fp16 conversion ----------------
__global__ void rope_h_kernel(const float* __restrict__ q, const float* __restrict__ k,
                              const float* __restrict__ v,
                              __half* __restrict__ qh, __half* __restrict__ kh,
                              __half* __restrict__ vh)
{
    int idx = blockIdx.x * blockDim.x + threadIdx.x;
    const int total = NTOK * NH * (HD / 2);
    if (idx >= total) return;
    int i   = idx & 31;
    int h   = (idx >> 5) & 15;
    int tok = idx >> 9;
    int l   = tok & (LL - 1);
    size_t base = (size_t)tok * DM + h * HD + 2 * i;

    float q1 = q[base], q2 = q[base + 1];
    float k1 = k[base], k2 = k[base + 1];
    if (h < 8) {
        double invf = pow(10000.0, -(double)i / 32.0);
        double ang = (double)l * invf;
        float cs = (float)cos(ang);
        float sn = (float)sin(ang);
        float qe = q1 * cs - q2 * sn;
        float qo = q1 * sn + q2 * cs;
        float ke = k1 * cs - k2 * sn;
        float ko = k1 * sn + k2 * cs;
        q1 = qe; q2 = qo; k1 = ke; k2 = ko;
    }
    qh[base]     = __float2half_rn(q1 * 0.125f);
    qh[base + 1] = __float2half_rn(q2 * 0.125f);
    kh[base]     = __float2half_rn(k1);
    kh[base + 1] = __float2half_rn(k2);
    vh[base]     = __float2half_rn(v[base]);
    vh[base + 1] = __float2half_rn(v[base + 1]);
}

// ---------------- tf32 tensor-core GEMM (R6, unchanged) ----------------
#define GA_STRIDE 36
#define GB_STRIDE 136
#define GA_FLOATS (128*GA_STRIDE)
#define GB_FLOATS (32*GB_STRIDE)
#define STAGE_FLOATS (GA_FLOATS + GB_FLOATS)
#define GEMM_SMEM (3*STAGE_FLOATS*4)

template<bool RELU, bool RES, bool ROUND>
__global__ __launch_bounds__(128, 2)
void tgemm(const float* __restrict__ A, const float* __restrict__ Bm,
           const float* __restrict__ bias, const float* __restrict__ res,
           float* __restrict__ C, int M, int N, int K)
{
    extern __shared__ float dsm[];
    int t = threadIdx.x;
    int wid = t >> 5, lane = t & 31;
    int g = lane >> 2, tq = lane & 3;
    int m0 = blockIdx.y * 128, n0 = blockIdx.x * 128;
    int wm = (wid >> 1) * 64;
    int wn = (wid & 1) * 64;

    float acc[4][8][4];
#pragma unroll
    for (int i = 0; i < 4; i++)
#pragma unroll
        for (int j = 0; j < 8; j++)
#pragma unroll
            for (int c = 0; c < 4; c++) acc[i][j][c] = 0.f;

    const int NK = K >> 5;

#pragma unroll
    for (int s = 0; s < 2; s++) {
        float* as = dsm + s * STAGE_FLOATS;
        float* bs = as + GA_FLOATS;
        int kb = s << 5;
#pragma unroll
        for (int u = 0; u < 8; u++) {
            int i = t + u * 128;
            int row = i >> 3, ch = i & 7;
            cp16(&as[row*GA_STRIDE + ch*4], A + (size_t)(m0 + row) * K + kb + ch * 4);
        }
#pragma unroll
        for (int u = 0; u < 8; u++) {
            int i = t + u * 128;
            int row = i >> 5, c4 = i & 31;
            cp16(&bs[row*GB_STRIDE + c4*4], Bm + (size_t)(kb + row) * N + n0 + c4 * 4);
        }
        CP_COMMIT();
    }

    for (int j = 0; j < NK; j++) {
        if (j + 2 < NK) { CP_WAIT1(); } else { CP_WAIT0(); }
        __syncthreads();

        int buf = j % 3;
        const uint32_t* as = (const uint32_t*)(dsm + buf * STAGE_FLOATS);
        const uint32_t* bs = as + GA_FLOATS;

#pragma unroll
        for (int kf = 0; kf < 4; kf++) {
            uint32_t bf[8][2];
#pragma unroll
            for (int nf = 0; nf < 8; nf++) {
                bf[nf][0] = bs[(kf*8 + tq)    *GB_STRIDE + wn + nf*8 + g];
                bf[nf][1] = bs[(kf*8 + tq + 4)*GB_STRIDE + wn + nf*8 + g];
            }
#pragma unroll
            for (int mf = 0; mf < 4; mf++) {
                int row = wm + mf * 16;
                uint32_t a0 = as[(row + g)    *GA_STRIDE + kf*8 + tq];
                uint32_t a1 = as[(row + g + 8)*GA_STRIDE + kf*8 + tq];
                uint32_t a2 = as[(row + g)    *GA_STRIDE + kf*8 + tq + 4];
                uint32_t a3 = as[(row + g + 8)*GA_STRIDE + kf*8 + tq + 4];
#pragma unroll
                for (int nf = 0; nf < 8; nf++)
                    mma8(acc[mf][nf][0], acc[mf][nf][1], acc[mf][nf][2], acc[mf][nf][3],
                         a0, a1, a2, a3, bf[nf][0], bf[nf][1]);
            }
        }

        if (j + 2 < NK) {
            int s = (j + 2) % 3;
            float* asw = dsm + s * STAGE_FLOATS;
            float* bsw = asw + GA_FLOATS;
            int kb = (j + 2) << 5;
#pragma unroll
            for (int u = 0; u < 8; u++) {
                int i = t + u * 128;
                int row = i >> 3, ch = i & 7;
                cp16(&asw[row*GA_STRIDE + ch*4], A + (size_t)(m0 + row) * K + kb + ch * 4);
            }
#pragma unroll
            for (int u = 0; u < 8; u++) {
                int i = t + u * 128;
                int row = i >> 5, c4 = i & 31;
                cp16(&bsw[row*GB_STRIDE + c4*4], Bm + (size_t)(kb + row) * N + n0 + c4 * 4);
            }
            CP_COMMIT();
        }
    }

#pragma unroll
    for (int mf = 0; mf < 4; mf++) {
#pragma unroll
        for (int nf = 0; nf < 8; nf++) {
            int r0 = m0 + wm + mf*16 + g;
            int r1 = r0 + 8;
            int cN = n0 + wn + nf*8 + 2*tq;
            float b0v = bias[cN], b1v = bias[cN + 1];
            float v0 = acc[mf][nf][0] + b0v;
            float v1 = acc[mf][nf][1] + b1v;
            float v2 = acc[mf][nf][2] + b0v;
            float v3 = acc[mf][nf][3] + b1v;
            if (RES) {
                v0 += res[(size_t)r0 * N + cN];     v1 += res[(size_t)r0 * N + cN + 1];
                v2 += res[(size_t)r1 * N + cN];     v3 += res[(size_t)r1 * N + cN + 1];
            }
            if (RELU) {
                v0 = fmaxf(v0, 0.f); v1 = fmaxf(v1, 0.f);
                v2 = fmaxf(v2, 0.f); v3 = fmaxf(v3, 0.f);
            }
            if (ROUND) {
                v0 = tf32f(v0); v1 = tf32f(v1); v2 = tf32f(v2); v3 = tf32f(v3);
            }
            *(float2*)(C + (size_t)r0 * N + cN) = make_float2(v0, v1);
            *(float2*)(C + (size_t)r1 * N + cN) = make_float2(v2, v3);
        }
    }
}

// ---------------- fp16 flash attention ----------------
// 64 q-rows per block, 128 threads = 4 warps x 16 rows.
// Qs/Ks/Vs: 64 x 72 halves (pad 8). P lives in registers (C->A fragment identity).
#define HS 72   // half stride

__global__ __launch_bounds__(128, 3)
void attn_kernel(const __half* __restrict__ q, const __half* __restrict__ k,
                 const __half* __restrict__ v, float* __restrict__ o)
{
    __shared__ __half Qs[64*HS];
    __shared__ __half Ks[2][64*HS];
    __shared__ __half Vs[2][64*HS];

    int qt = blockIdx.x, h = blockIdx.y, b = blockIdx.z;
    int t = threadIdx.x;
    int wid = t >> 5, lane = t & 31;
    int g = lane >> 2, tq = lane & 3;
    int wq = wid * 16;

    const __half* qbh = q + ((size_t)b * LL + qt * 64) * DM + h * HD;
    const __half* kbh = k + (size_t)b * LL * DM + h * HD;
    const __half* vbh = v + (size_t)b * LL * DM + h * HD;

    // prologue: Q + K0 + V0 (rows of 64 halves = 8 x 16B chunks)
#pragma unroll
    for (int u = 0; u < 4; u++) {
        int i = t + u * 128;
        int rr = i >> 3, c8 = i & 7;
        cp16(&Qs[rr*HS + c8*8],    qbh + (size_t)rr * DM + c8 * 8);
        cp16(&Ks[0][rr*HS + c8*8], kbh + (size_t)rr * DM + c8 * 8);
        cp16(&Vs[0][rr*HS + c8*8], vbh + (size_t)rr * DM + c8 * 8);
    }
    CP_COMMIT(); CP_WAIT0(); __syncthreads();

    // hoist Q fragments (4 k-steps of 16)
    uint32_t qa[4][4];
    {
        const uint32_t* qs = (const uint32_t*)Qs;
#pragma unroll
        for (int kf = 0; kf < 4; kf++) {
            qa[kf][0] = qs[(wq + g)    *(HS/2) + kf*8 + tq];
            qa[kf][1] = qs[(wq + g + 8)*(HS/2) + kf*8 + tq];
            qa[kf][2] = qs[(wq + g)    *(HS/2) + kf*8 + tq + 4];
            qa[kf][3] = qs[(wq + g + 8)*(HS/2) + kf*8 + tq + 4];
        }
    }

    // per-lane ldmatrix offsets for V (trans)
    int row_off = ((lane >> 3) & 1) * 8 + (lane & 7);
    int col_off = (lane >> 4) * 8;

    float oacc[8][4];
#pragma unroll
    for (int i = 0; i < 8; i++)
#pragma unroll
        for (int c = 0; c < 4; c++) oacc[i][c] = 0.f;
    float m0 = -1e30f, m1 = -1e30f, l0 = 0.f, l1 = 0.f;

    for (int j = 0; j < LL/64; j++) {
        int cur = j & 1;
        if (j + 1 < LL/64) {
            int nxt = cur ^ 1;
            const __half* kn = kbh + (size_t)(j + 1) * 64 * DM;
            const __half* vn = vbh + (size_t)(j + 1) * 64 * DM;
#pragma unroll
            for (int u = 0; u < 4; u++) {
                int i = t + u * 128;
                int rr = i >> 3, c8 = i & 7;
                cp16(&Ks[nxt][rr*HS + c8*8], kn + (size_t)rr * DM + c8 * 8);
                cp16(&Vs[nxt][rr*HS + c8*8], vn + (size_t)rr * DM + c8 * 8);
            }
        }
        CP_COMMIT();

        // ---- S = Q @ K^T (fp16, fp32 accum) ----
        const uint32_t* ks = (const uint32_t*)Ks[cur];
        float sacc[8][4];
#pragma unroll
        for (int i = 0; i < 8; i++)
#pragma unroll
            for (int c = 0; c < 4; c++) sacc[i][c] = 0.f;

#pragma unroll
        for (int kf = 0; kf < 4; kf++) {
#pragma unroll
            for (int nf = 0; nf < 8; nf++) {
                uint32_t b0 = ks[(nf*8 + g)*(HS/2) + kf*8 + tq];
                uint32_t b1 = ks[(nf*8 + g)*(HS/2) + kf*8 + tq + 4];
                mma16(sacc[nf][0], sacc[nf][1], sacc[nf][2], sacc[nf][3],
                      qa[kf][0], qa[kf][1], qa[kf][2], qa[kf][3], b0, b1);
            }
        }

        // ---- online softmax; P packed to half2 fragments in registers ----
        float mx0 = -1e30f, mx1 = -1e30f;
#pragma unroll
        for (int nf = 0; nf < 8; nf++) {
            mx0 = fmaxf(mx0, fmaxf(sacc[nf][0], sacc[nf][1]));
            mx1 = fmaxf(mx1, fmaxf(sacc[nf][2], sacc[nf][3]));
        }
        mx0 = fmaxf(mx0, __shfl_xor_sync(0xffffffffu, mx0, 1));
        mx0 = fmaxf(mx0, __shfl_xor_sync(0xffffffffu, mx0, 2));
        mx1 = fmaxf(mx1, __shfl_xor_sync(0xffffffffu, mx1, 1));
        mx1 = fmaxf(mx1, __shfl_xor_sync(0xffffffffu, mx1, 2));
        float mn0 = fmaxf(m0, mx0), mn1 = fmaxf(m1, mx1);
        float al0 = __expf(m0 - mn0), al1 = __expf(m1 - mn1);

        uint32_t pa[8][2];
        float sum0 = 0.f, sum1 = 0.f;
#pragma unroll
        for (int nf = 0; nf < 8; nf++) {
            float p0 = __expf(sacc[nf][0] - mn0);
            float p1 = __expf(sacc[nf][1] - mn0);
            float p2 = __expf(sacc[nf][2] - mn1);
            float p3 = __expf(sacc[nf][3] - mn1);
            sum0 += p0 + p1;
            sum1 += p2 + p3;
            pa[nf][0] = pack_h2(p0, p1);
            pa[nf][1] = pack_h2(p2, p3);
        }
        sum0 += __shfl_xor_sync(0xffffffffu, sum0, 1);
        sum0 += __shfl_xor_sync(0xffffffffu, sum0, 2);
        sum1 += __shfl_xor_sync(0xffffffffu, sum1, 1);
        sum1 += __shfl_xor_sync(0xffffffffu, sum1, 2);
        l0 = l0 * al0 + sum0;
        l1 = l1 * al1 + sum1;
        m0 = mn0; m1 = mn1;
#pragma unroll
        for (int nf = 0; nf < 8; nf++) {
            oacc[nf][0] *= al0; oacc[nf][1] *= al0;
            oacc[nf][2] *= al1; oacc[nf][3] *= al1;
        }

        // ---- O += P @ V (V fragments via ldmatrix.x4.trans) ----
        uint32_t vs_base = (uint32_t)__cvta_generic_to_shared(&Vs[cur][0]);
#pragma unroll
        for (int kf = 0; kf < 4; kf++) {
            uint32_t a0 = pa[2*kf][0],   a1 = pa[2*kf][1];
            uint32_t a2 = pa[2*kf+1][0], a3 = pa[2*kf+1][1];
#pragma unroll
            for (int np = 0; np < 4; np++) {
                uint32_t addr = vs_base +
                    (uint32_t)(((kf*16 + row_off)*HS + np*16 + col_off) * 2);
                uint32_t r0, r1, r2, r3;
                ldmx4t(r0, r1, r2, r3, addr);
                mma16(oacc[2*np][0],   oacc[2*np][1],   oacc[2*np][2],   oacc[2*np][3],
                      a0, a1, a2, a3, r0, r1);
                mma16(oacc[2*np+1][0], oacc[2*np+1][1], oacc[2*np+1][2], oacc[2*np+1][3],
                      a0, a1, a2, a3, r2, r3);
            }
        }

        CP_WAIT0();
        __syncthreads();
    }

    float inv0 = 1.f / l0, inv1 = 1.f / l1;
    size_t row0 = (size_t)b * LL + qt * 64 + wq + g;
    size_t row1 = row0 + 8;
#pragma unroll
    for (int nf = 0; nf < 8; nf++) {
        int cN = h * HD + nf*8 + 2*tq;
        *(float2*)(o + row0 * DM + cN) =
            make_float2(tf32f(oacc[nf][0] * inv0), tf32f(oacc[nf][1] * inv0));
        *(float2*)(o + row1 * DM + cN) =
            make_float2(tf32f(oacc[nf][2] * inv1), tf32f(oacc[nf][3] * inv1));
    }
}

// ---------------- launcher ----------------
extern "C" void kernel_launch(void* const* d_in, const int* in_sizes, int n_in,
                              void* d_out, int out_size)
{
    const float* x     = (const float*)d_in[0];
    const float* Wq    = (const float*)d_in[1];
    const float* bq    = (const float*)d_in[2];
    const float* Wk    = (const float*)d_in[3];
    const float* bk    = (const float*)d_in[4];
    const float* Wv    = (const float*)d_in[5];
    const float* bv    = (const float*)d_in[6];
    const float* Wo    = (const float*)d_in[7];
    const float* bo    = (const float*)d_in[8];
    const float* ln1_g = (const float*)d_in[9];
    const float* ln1_b = (const float*)d_in[10];
    const float* ln2_g = (const float*)d_in[11];
    const float* ln2_b = (const float*)d_in[12];
    const float* W1    = (const float*)d_in[13];
    const float* b1    = (const float*)d_in[14];
    const float* W2    = (const float*)d_in[15];
    const float* b2    = (const float*)d_in[16];
    float* out = (float*)d_out;

    float *xn, *q, *k, *v, *o, *x2, *xn2, *hb;
    float *xr, *wq, *wk, *wv, *wo, *w1, *w2;
    __half *qh, *kh, *vh;
    cudaGetSymbolAddress((void**)&xn,  g_xn);
    cudaGetSymbolAddress((void**)&q,   g_q);
    cudaGetSymbolAddress((void**)&k,   g_k);
    cudaGetSymbolAddress((void**)&v,   g_v);
    cudaGetSymbolAddress((void**)&o,   g_o);
    cudaGetSymbolAddress((void**)&x2,  g_x2);
    cudaGetSymbolAddress((void**)&xn2, g_xn2);
    cudaGetSymbolAddress((void**)&hb,  g_h);
    cudaGetSymbolAddress((void**)&xr,  g_xr);
    cudaGetSymbolAddress((void**)&wq,  g_wq);
    cudaGetSymbolAddress((void**)&wk,  g_wk);
    cudaGetSymbolAddress((void**)&wv,  g_wv);
    cudaGetSymbolAddress((void**)&wo,  g_wo);
    cudaGetSymbolAddress((void**)&w1,  g_w1);
    cudaGetSymbolAddress((void**)&w2,  g_w2);
    cudaGetSymbolAddress((void**)&qh,  g_qh);
    cudaGetSymbolAddress((void**)&kh,  g_kh);
    cudaGetSymbolAddress((void**)&vh,  g_vh);

    static bool attr_set = false;
    if (!attr_set) {
        cudaFuncSetAttribute((const void*)tgemm<false,false,false>, cudaFuncAttributeMaxDynamicSharedMemorySize, GEMM_SMEM);
        cudaFuncSetAttribute((const void*)tgemm<false,true,false>,  cudaFuncAttributeMaxDynamicSharedMemorySize, GEMM_SMEM);
        cudaFuncSetAttribute((const void*)tgemm<true,false,true>,   cudaFuncAttributeMaxDynamicSharedMemorySize, GEMM_SMEM);
        attr_set = true;
    }

    // round external operands to tf32-representable fp32
    round_tf32_kernel<<<(NTOK*DM/4 + 255)/256, 256>>>(x,  xr, NTOK*DM/4);
    round_tf32_kernel<<<(DM*DM/4   + 255)/256, 256>>>(Wq, wq, DM*DM/4);
    round_tf32_kernel<<<(DM*DM/4   + 255)/256, 256>>>(Wk, wk, DM*DM/4);
    round_tf32_kernel<<<(DM*DM/4   + 255)/256, 256>>>(Wv, wv, DM*DM/4);
    round_tf32_kernel<<<(DM*DM/4   + 255)/256, 256>>>(Wo, wo, DM*DM/4);
    round_tf32_kernel<<<(DM*DFF/4  + 255)/256, 256>>>(W1, w1, DM*DFF/4);
    round_tf32_kernel<<<(DFF*DM/4  + 255)/256, 256>>>(W2, w2, DFF*DM/4);

    ln_kernel<<<NTOK, 256>>>(x, ln1_g, ln1_b, xn);

    dim3 g1(DM / 128, NTOK / 128);     // (8, 32)
    tgemm<false,false,false><<<g1, 128, GEMM_SMEM>>>(xn, wq, bq, nullptr, q, NTOK, DM, DM);
    tgemm<false,false,false><<<g1, 128, GEMM_SMEM>>>(xr, wk, bk, nullptr, k, NTOK, DM, DM);
    tgemm<false,false,false><<<g1, 128, GEMM_SMEM>>>(xr, wv, bv, nullptr, v, NTOK, DM, DM);

    const int pairs = NTOK * NH * (HD / 2);
    rope_h_kernel<<<(pairs + 255) / 256, 256>>>(q, k, v, qh, kh, vh);

    dim3 ga(LL / 64, NH, BB);
    attn_kernel<<<ga, 128>>>(qh, kh, vh, o);

    tgemm<false,true,false><<<g1, 128, GEMM_SMEM>>>(o, wo, bo, x, x2, NTOK, DM, DM);

    ln_kernel<<<NTOK, 256>>>(x2, ln2_g, ln2_b, xn2);

    dim3 g2(DFF / 128, NTOK / 128);    // (32, 32)
    tgemm<true,false,true><<<g2, 128, GEMM_SMEM>>>(xn2, w1, b1, nullptr, hb, NTOK, DFF, DM);
    tgemm<false,true,false><<<g1, 128, GEMM_SMEM>>>(hb, w2, b2, x2, out, NTOK, DM, DFF);
}

// round 8
// speedup vs baseline: 14.4849x; 1.2755x over previous
#include <cuda_runtime.h>
#include <cuda_fp16.h>
#include <math.h>
#include <stdint.h>

#define BB 2
#define LL 2048
#define DM 1024
#define NH 16
#define HD 64
#define DFF 4096
#define NTOK (BB*LL)
#define LN_EPS 1e-5f

// ---------------- scratch (no allocation allowed) ----------------
__device__ float  g_x2 [NTOK*DM];
__device__ __half g_xh [NTOK*DM];
__device__ __half g_xnh[NTOK*DM];
__device__ __half g_qh [NTOK*DM];
__device__ __half g_kh [NTOK*DM];
__device__ __half g_vh [NTOK*DM];
__device__ __half g_oh [NTOK*DM];
__device__ __half g_xn2h[NTOK*DM];
__device__ __half g_hbh[NTOK*DFF];
// transposed half weights [N][K]
__device__ __half g_wqh[DM*DM];
__device__ __half g_wkh[DM*DM];
__device__ __half g_wvh[DM*DM];
__device__ __half g_woh[DM*DM];
__device__ __half g_w1h[DFF*DM];
__device__ __half g_w2h[DM*DFF];

// ---------------- helpers ----------------
__device__ __forceinline__ void cp16(void* smem, const void* g) {
    unsigned sa = (unsigned)__cvta_generic_to_shared(smem);
    asm volatile("cp.async.cg.shared.global [%0], [%1], 16;" :: "r"(sa), "l"(g));
}
#define CP_COMMIT() asm volatile("cp.async.commit_group;" ::: "memory")
#define CP_WAIT0()  asm volatile("cp.async.wait_group 0;" ::: "memory")
#define CP_WAIT1()  asm volatile("cp.async.wait_group 1;" ::: "memory")

__device__ __forceinline__ void mma16(float& c0, float& c1, float& c2, float& c3,
                                      uint32_t a0, uint32_t a1, uint32_t a2, uint32_t a3,
                                      uint32_t b0, uint32_t b1) {
    asm("mma.sync.aligned.m16n8k16.row.col.f32.f16.f16.f32 "
        "{%0,%1,%2,%3},{%4,%5,%6,%7},{%8,%9},{%0,%1,%2,%3};"
        : "+f"(c0), "+f"(c1), "+f"(c2), "+f"(c3)
        : "r"(a0), "r"(a1), "r"(a2), "r"(a3), "r"(b0), "r"(b1));
}
__device__ __forceinline__ uint32_t pack_h2(float x, float y) {
    uint32_t r;
    asm("cvt.rn.f16x2.f32 %0, %1, %2;" : "=r"(r) : "f"(y), "f"(x));
    return r;
}
__device__ __forceinline__ void ldmx4t(uint32_t& r0, uint32_t& r1, uint32_t& r2, uint32_t& r3,
                                       uint32_t addr) {
    asm volatile("ldmatrix.sync.aligned.m8n8.x4.trans.shared.b16 {%0,%1,%2,%3}, [%4];"
                 : "=r"(r0), "=r"(r1), "=r"(r2), "=r"(r3) : "r"(addr));
}

// ---------------- operand conditioning ----------------
__global__ void f2h_kernel(const float* __restrict__ in, __half* __restrict__ out, int n4)
{
    int i = blockIdx.x * blockDim.x + threadIdx.x;
    if (i >= n4) return;
    float4 v = ((const float4*)in)[i];
    uint32_t lo = pack_h2(v.x, v.y), hi = pack_h2(v.z, v.w);
    ((uint2*)out)[i] = make_uint2(lo, hi);
}

// in: [K][N] fp32 row-major; out: [N][K] half row-major
__global__ void transpose_h_kernel(const float* __restrict__ in, __half* __restrict__ out,
                                   int K, int N)
{
    __shared__ float tile[32][33];
    int n0 = blockIdx.x * 32, k0 = blockIdx.y * 32;
#pragma unroll
    for (int i = threadIdx.y; i < 32; i += 8)
        tile[i][threadIdx.x] = in[(size_t)(k0 + i) * N + n0 + threadIdx.x];
    __syncthreads();
#pragma unroll
    for (int i = threadIdx.y; i < 32; i += 8)
        out[(size_t)(n0 + i) * K + k0 + threadIdx.x] = __float2half_rn(tile[threadIdx.x][i]);
}

// ---------------- LayerNorm (fp32 in, half out) ----------------
__global__ void ln_kernel(const float* __restrict__ x, const float* __restrict__ g,
                          const float* __restrict__ b, __half* __restrict__ y)
{
    int row = blockIdx.x;
    int t = threadIdx.x;
    const float4* xr = (const float4*)(x + (size_t)row * DM);
    float4 v = xr[t];
    float s  = v.x + v.y + v.z + v.w;
    float ss = v.x*v.x + v.y*v.y + v.z*v.z + v.w*v.w;
#pragma unroll
    for (int o = 16; o; o >>= 1) {
        s  += __shfl_xor_sync(0xffffffffu, s,  o);
        ss += __shfl_xor_sync(0xffffffffu, ss, o);
    }
    __shared__ float sh_s[8], sh_ss[8];
    int w = t >> 5, lane = t & 31;
    if (lane == 0) { sh_s[w] = s; sh_ss[w] = ss; }
    __syncthreads();
    if (t < 32) {
        s  = (t < 8) ? sh_s[t]  : 0.f;
        ss = (t < 8) ? sh_ss[t] : 0.f;
#pragma unroll
        for (int o = 4; o; o >>= 1) {
            s  += __shfl_xor_sync(0xffffffffu, s,  o);
            ss += __shfl_xor_sync(0xffffffffu, ss, o);
        }
        if (t == 0) { sh_s[0] = s; sh_ss[0] = ss; }
    }
    __syncthreads();
    float mu  = sh_s[0] * (1.f / DM);
    float var = sh_ss[0] * (1.f / DM) - mu * mu;
    float inv = rsqrtf(var + LN_EPS);
    float4 gv = ((const float4*)g)[t];
    float4 bv = ((const float4*)b)[t];
    uint32_t lo = pack_h2((v.x - mu) * inv * gv.x + bv.x,
                          (v.y - mu) * inv * gv.y + bv.y);
    uint32_t hi = pack_h2((v.z - mu) * inv * gv.z + bv.z,
                          (v.w - mu) * inv * gv.w + bv.w);
    ((uint2*)(y + (size_t)row * DM))[t] = make_uint2(lo, hi);
}

// ---------------- RoPE (heads < 8) + q scale, half in/out ----------------
__global__ void rope_h_kernel(__half* __restrict__ q, __half* __restrict__ k)
{
    int idx = blockIdx.x * blockDim.x + threadIdx.x;
    const int total = NTOK * NH * (HD / 2);
    if (idx >= total) return;
    int i   = idx & 31;
    int h   = (idx >> 5) & 15;
    int tok = idx >> 9;
    int l   = tok & (LL - 1);
    size_t base = (size_t)tok * DM + h * HD + 2 * i;

    float q1 = __half2float(q[base]), q2 = __half2float(q[base + 1]);
    if (h < 8) {
        double invf = pow(10000.0, -(double)i / 32.0);
        double ang = (double)l * invf;
        float cs = (float)cos(ang);
        float sn = (float)sin(ang);
        float k1 = __half2float(k[base]), k2 = __half2float(k[base + 1]);
        float qe = q1 * cs - q2 * sn;
        float qo = q1 * sn + q2 * cs;
        q1 = qe; q2 = qo;
        k[base]     = __float2half_rn(k1 * cs - k2 * sn);
        k[base + 1] = __float2half_rn(k1 * sn + k2 * cs);
    }
    q[base]     = __float2half_rn(q1 * 0.125f);
    q[base + 1] = __float2half_rn(q2 * 0.125f);
}

// ---------------- fp16 tensor-core GEMM ----------------
// C[M,N] = A[M,K] @ Bt[N,K]^T + bias (+res fp32) (relu); C half or fp32.
// 128x128 tile, 128 threads = 4 warps (2m x 2n), warp tile 64x64, BK=32,
// 3-stage cp.async ring. A/B smem rows: 40 halves (stride 20 words, conflict-free).
#define AS_H 40
#define STAGE_H (128*AS_H*2)          // halves per stage (A+B) = 10240
#define HGEMM_SMEM (3*STAGE_H*2)      // 61440 bytes

template<bool RELU, bool RES, bool HALF_OUT>
__global__ __launch_bounds__(128, 2)
void hgemm(const __half* __restrict__ A, const __half* __restrict__ Bt,
           const float* __restrict__ bias, const float* __restrict__ res,
           void* __restrict__ Cv, int M, int N, int K)
{
    extern __shared__ __half hsm[];
    int t = threadIdx.x;
    int wid = t >> 5, lane = t & 31;
    int g = lane >> 2, tq = lane & 3;
    int m0 = blockIdx.y * 128, n0 = blockIdx.x * 128;
    int wm = (wid >> 1) * 64;
    int wn = (wid & 1) * 64;

    float acc[4][8][4];
#pragma unroll
    for (int i = 0; i < 4; i++)
#pragma unroll
        for (int j = 0; j < 8; j++)
#pragma unroll
            for (int c = 0; c < 4; c++) acc[i][j][c] = 0.f;

    const int NK = K >> 5;

    // prologue: stages 0,1
#pragma unroll
    for (int s = 0; s < 2; s++) {
        __half* as = hsm + s * STAGE_H;
        __half* bs = as + 128 * AS_H;
        int kb = s << 5;
#pragma unroll
        for (int u = 0; u < 4; u++) {
            int i = t + u * 128;
            int row = i >> 2, ch = i & 3;
            cp16(&as[row*AS_H + ch*8], A  + (size_t)(m0 + row) * K + kb + ch * 8);
            cp16(&bs[row*AS_H + ch*8], Bt + (size_t)(n0 + row) * K + kb + ch * 8);
        }
        CP_COMMIT();
    }

    for (int j = 0; j < NK; j++) {
        if (j + 2 < NK) { CP_WAIT1(); } else { CP_WAIT0(); }
        __syncthreads();

        int buf = j % 3;
        const uint32_t* as = (const uint32_t*)(hsm + buf * STAGE_H);
        const uint32_t* bs = as + 128 * (AS_H/2);

#pragma unroll
        for (int kf = 0; kf < 2; kf++) {
            uint32_t bf[8][2];
#pragma unroll
            for (int nf = 0; nf < 8; nf++) {
                bf[nf][0] = bs[(wn + nf*8 + g)*(AS_H/2) + kf*8 + tq];
                bf[nf][1] = bs[(wn + nf*8 + g)*(AS_H/2) + kf*8 + tq + 4];
            }
#pragma unroll
            for (int mf = 0; mf < 4; mf++) {
                int row = wm + mf * 16;
                uint32_t a0 = as[(row + g)    *(AS_H/2) + kf*8 + tq];
                uint32_t a1 = as[(row + g + 8)*(AS_H/2) + kf*8 + tq];
                uint32_t a2 = as[(row + g)    *(AS_H/2) + kf*8 + tq + 4];
                uint32_t a3 = as[(row + g + 8)*(AS_H/2) + kf*8 + tq + 4];
#pragma unroll
                for (int nf = 0; nf < 8; nf++)
                    mma16(acc[mf][nf][0], acc[mf][nf][1], acc[mf][nf][2], acc[mf][nf][3],
                          a0, a1, a2, a3, bf[nf][0], bf[nf][1]);
            }
        }

        if (j + 2 < NK) {
            int s = (j + 2) % 3;
            __half* asw = hsm + s * STAGE_H;
            __half* bsw = asw + 128 * AS_H;
            int kb = (j + 2) << 5;
#pragma unroll
            for (int u = 0; u < 4; u++) {
                int i = t + u * 128;
                int row = i >> 2, ch = i & 3;
                cp16(&asw[row*AS_H + ch*8], A  + (size_t)(m0 + row) * K + kb + ch * 8);
                cp16(&bsw[row*AS_H + ch*8], Bt + (size_t)(n0 + row) * K + kb + ch * 8);
            }
            CP_COMMIT();
        }
    }

    // epilogue
#pragma unroll
    for (int mf = 0; mf < 4; mf++) {
#pragma unroll
        for (int nf = 0; nf < 8; nf++) {
            int r0 = m0 + wm + mf*16 + g;
            int r1 = r0 + 8;
            int cN = n0 + wn + nf*8 + 2*tq;
            float b0v = bias[cN], b1v = bias[cN + 1];
            float v0 = acc[mf][nf][0] + b0v;
            float v1 = acc[mf][nf][1] + b1v;
            float v2 = acc[mf][nf][2] + b0v;
            float v3 = acc[mf][nf][3] + b1v;
            if (RES) {
                v0 += res[(size_t)r0 * N + cN];     v1 += res[(size_t)r0 * N + cN + 1];
                v2 += res[(size_t)r1 * N + cN];     v3 += res[(size_t)r1 * N + cN + 1];
            }
            if (RELU) {
                v0 = fmaxf(v0, 0.f); v1 = fmaxf(v1, 0.f);
                v2 = fmaxf(v2, 0.f); v3 = fmaxf(v3, 0.f);
            }
            if (HALF_OUT) {
                __half* C = (__half*)Cv;
                *(uint32_t*)(C + (size_t)r0 * N + cN) = pack_h2(v0, v1);
                *(uint32_t*)(C + (size_t)r1 * N + cN) = pack_h2(v2, v3);
            } else {
                float* C = (float*)Cv;
                *(float2*)(C + (size_t)r0 * N + cN) = make_float2(v0, v1);
                *(float2*)(C + (size_t)r1 * N + cN) = make_float2(v2, v3);
            }
        }
    }
}

// ---------------- fp16 flash attention (R7; half output) ----------------
#define HS 72   // half stride

__global__ __launch_bounds__(128, 3)
void attn_kernel(const __half* __restrict__ q, const __half* __restrict__ k,
                 const __half* __restrict__ v, __half* __restrict__ o)
{
    __shared__ __half Qs[64*HS];
    __shared__ __half Ks[2][64*HS];
    __shared__ __half Vs[2][64*HS];

    int qt = blockIdx.x, h = blockIdx.y, b = blockIdx.z;
    int t = threadIdx.x;
    int wid = t >> 5, lane = t & 31;
    int g = lane >> 2, tq = lane & 3;
    int wq = wid * 16;

    const __half* qbh = q + ((size_t)b * LL + qt * 64) * DM + h * HD;
    const __half* kbh = k + (size_t)b * LL * DM + h * HD;
    const __half* vbh = v + (size_t)b * LL * DM + h * HD;

#pragma unroll
    for (int u = 0; u < 4; u++) {
        int i = t + u * 128;
        int rr = i >> 3, c8 = i & 7;
        cp16(&Qs[rr*HS + c8*8],    qbh + (size_t)rr * DM + c8 * 8);
        cp16(&Ks[0][rr*HS + c8*8], kbh + (size_t)rr * DM + c8 * 8);
        cp16(&Vs[0][rr*HS + c8*8], vbh + (size_t)rr * DM + c8 * 8);
    }
    CP_COMMIT(); CP_WAIT0(); __syncthreads();

    uint32_t qa[4][4];
    {
        const uint32_t* qs = (const uint32_t*)Qs;
#pragma unroll
        for (int kf = 0; kf < 4; kf++) {
            qa[kf][0] = qs[(wq + g)    *(HS/2) + kf*8 + tq];
            qa[kf][1] = qs[(wq + g + 8)*(HS/2) + kf*8 + tq];
            qa[kf][2] = qs[(wq + g)    *(HS/2) + kf*8 + tq + 4];
            qa[kf][3] = qs[(wq + g + 8)*(HS/2) + kf*8 + tq + 4];
        }
    }

    int row_off = ((lane >> 3) & 1) * 8 + (lane & 7);
    int col_off = (lane >> 4) * 8;

    float oacc[8][4];
#pragma unroll
    for (int i = 0; i < 8; i++)
#pragma unroll
        for (int c = 0; c < 4; c++) oacc[i][c] = 0.f;
    float m0 = -1e30f, m1 = -1e30f, l0 = 0.f, l1 = 0.f;

    for (int j = 0; j < LL/64; j++) {
        int cur = j & 1;
        if (j + 1 < LL/64) {
            int nxt = cur ^ 1;
            const __half* kn = kbh + (size_t)(j + 1) * 64 * DM;
            const __half* vn = vbh + (size_t)(j + 1) * 64 * DM;
#pragma unroll
            for (int u = 0; u < 4; u++) {
                int i = t + u * 128;
                int rr = i >> 3, c8 = i & 7;
                cp16(&Ks[nxt][rr*HS + c8*8], kn + (size_t)rr * DM + c8 * 8);
                cp16(&Vs[nxt][rr*HS + c8*8], vn + (size_t)rr * DM + c8 * 8);
            }
        }
        CP_COMMIT();

        const uint32_t* ks = (const uint32_t*)Ks[cur];
        float sacc[8][4];
#pragma unroll
        for (int i = 0; i < 8; i++)
#pragma unroll
            for (int c = 0; c < 4; c++) sacc[i][c] = 0.f;

#pragma unroll
        for (int kf = 0; kf < 4; kf++) {
#pragma unroll
            for (int nf = 0; nf < 8; nf++) {
                uint32_t b0 = ks[(nf*8 + g)*(HS/2) + kf*8 + tq];
                uint32_t b1 = ks[(nf*8 + g)*(HS/2) + kf*8 + tq + 4];
                mma16(sacc[nf][0], sacc[nf][1], sacc[nf][2], sacc[nf][3],
                      qa[kf][0], qa[kf][1], qa[kf][2], qa[kf][3], b0, b1);
            }
        }

        float mx0 = -1e30f, mx1 = -1e30f;
#pragma unroll
        for (int nf = 0; nf < 8; nf++) {
            mx0 = fmaxf(mx0, fmaxf(sacc[nf][0], sacc[nf][1]));
            mx1 = fmaxf(mx1, fmaxf(sacc[nf][2], sacc[nf][3]));
        }
        mx0 = fmaxf(mx0, __shfl_xor_sync(0xffffffffu, mx0, 1));
        mx0 = fmaxf(mx0, __shfl_xor_sync(0xffffffffu, mx0, 2));
        mx1 = fmaxf(mx1, __shfl_xor_sync(0xffffffffu, mx1, 1));
        mx1 = fmaxf(mx1, __shfl_xor_sync(0xffffffffu, mx1, 2));
        float mn0 = fmaxf(m0, mx0), mn1 = fmaxf(m1, mx1);
        float al0 = __expf(m0 - mn0), al1 = __expf(m1 - mn1);

        uint32_t pa[8][2];
        float sum0 = 0.f, sum1 = 0.f;
#pragma unroll
        for (int nf = 0; nf < 8; nf++) {
            float p0 = __expf(sacc[nf][0] - mn0);
            float p1 = __expf(sacc[nf][1] - mn0);
            float p2 = __expf(sacc[nf][2] - mn1);
            float p3 = __expf(sacc[nf][3] - mn1);
            sum0 += p0 + p1;
            sum1 += p2 + p3;
            pa[nf][0] = pack_h2(p0, p1);
            pa[nf][1] = pack_h2(p2, p3);
        }
        sum0 += __shfl_xor_sync(0xffffffffu, sum0, 1);
        sum0 += __shfl_xor_sync(0xffffffffu, sum0, 2);
        sum1 += __shfl_xor_sync(0xffffffffu, sum1, 1);
        sum1 += __shfl_xor_sync(0xffffffffu, sum1, 2);
        l0 = l0 * al0 + sum0;
        l1 = l1 * al1 + sum1;
        m0 = mn0; m1 = mn1;
#pragma unroll
        for (int nf = 0; nf < 8; nf++) {
            oacc[nf][0] *= al0; oacc[nf][1] *= al0;
            oacc[nf][2] *= al1; oacc[nf][3] *= al1;
        }

        uint32_t vs_base = (uint32_t)__cvta_generic_to_shared(&Vs[cur][0]);
#pragma unroll
        for (int kf = 0; kf < 4; kf++) {
            uint32_t a0 = pa[2*kf][0],   a1 = pa[2*kf][1];
            uint32_t a2 = pa[2*kf+1][0], a3 = pa[2*kf+1][1];
#pragma unroll
            for (int np = 0; np < 4; np++) {
                uint32_t addr = vs_base +
                    (uint32_t)(((kf*16 + row_off)*HS + np*16 + col_off) * 2);
                uint32_t r0, r1, r2, r3;
                ldmx4t(r0, r1, r2, r3, addr);
                mma16(oacc[2*np][0],   oacc[2*np][1],   oacc[2*np][2],   oacc[2*np][3],
                      a0, a1, a2, a3, r0, r1);
                mma16(oacc[2*np+1][0], oacc[2*np+1][1], oacc[2*np+1][2], oacc[2*np+1][3],
                      a0, a1, a2, a3, r2, r3);
            }
        }

        CP_WAIT0();
        __syncthreads();
    }

    float inv0 = 1.f / l0, inv1 = 1.f / l1;
    size_t row0 = (size_t)b * LL + qt * 64 + wq + g;
    size_t row1 = row0 + 8;
#pragma unroll
    for (int nf = 0; nf < 8; nf++) {
        int cN = h * HD + nf*8 + 2*tq;
        *(uint32_t*)(o + row0 * DM + cN) = pack_h2(oacc[nf][0] * inv0, oacc[nf][1] * inv0);
        *(uint32_t*)(o + row1 * DM + cN) = pack_h2(oacc[nf][2] * inv1, oacc[nf][3] * inv1);
    }
}

// ---------------- launcher ----------------
extern "C" void kernel_launch(void* const* d_in, const int* in_sizes, int n_in,
                              void* d_out, int out_size)
{
    const float* x     = (const float*)d_in[0];
    const float* Wq    = (const float*)d_in[1];
    const float* bq    = (const float*)d_in[2];
    const float* Wk    = (const float*)d_in[3];
    const float* bk    = (const float*)d_in[4];
    const float* Wv    = (const float*)d_in[5];
    const float* bv    = (const float*)d_in[6];
    const float* Wo    = (const float*)d_in[7];
    const float* bo    = (const float*)d_in[8];
    const float* ln1_g = (const float*)d_in[9];
    const float* ln1_b = (const float*)d_in[10];
    const float* ln2_g = (const float*)d_in[11];
    const float* ln2_b = (const float*)d_in[12];
    const float* W1    = (const float*)d_in[13];
    const float* b1    = (const float*)d_in[14];
    const float* W2    = (const float*)d_in[15];
    const float* b2    = (const float*)d_in[16];
    float* out = (float*)d_out;

    float *x2;
    __half *xh, *xnh, *qh, *kh, *vh, *oh, *xn2h, *hbh;
    __half *wqh, *wkh, *wvh, *woh, *w1h, *w2h;
    cudaGetSymbolAddress((void**)&x2,   g_x2);
    cudaGetSymbolAddress((void**)&xh,   g_xh);
    cudaGetSymbolAddress((void**)&xnh,  g_xnh);
    cudaGetSymbolAddress((void**)&qh,   g_qh);
    cudaGetSymbolAddress((void**)&kh,   g_kh);
    cudaGetSymbolAddress((void**)&vh,   g_vh);
    cudaGetSymbolAddress((void**)&oh,   g_oh);
    cudaGetSymbolAddress((void**)&xn2h, g_xn2h);
    cudaGetSymbolAddress((void**)&hbh,  g_hbh);
    cudaGetSymbolAddress((void**)&wqh,  g_wqh);
    cudaGetSymbolAddress((void**)&wkh,  g_wkh);
    cudaGetSymbolAddress((void**)&wvh,  g_wvh);
    cudaGetSymbolAddress((void**)&woh,  g_woh);
    cudaGetSymbolAddress((void**)&w1h,  g_w1h);
    cudaGetSymbolAddress((void**)&w2h,  g_w2h);

    static bool attr_set = false;
    if (!attr_set) {
        cudaFuncSetAttribute((const void*)hgemm<false,false,true>, cudaFuncAttributeMaxDynamicSharedMemorySize, HGEMM_SMEM);
        cudaFuncSetAttribute((const void*)hgemm<false,true,false>, cudaFuncAttributeMaxDynamicSharedMemorySize, HGEMM_SMEM);
        cudaFuncSetAttribute((const void*)hgemm<true,false,true>,  cudaFuncAttributeMaxDynamicSharedMemorySize, HGEMM_SMEM);
        attr_set = true;
    }

    // operand conditioning: x -> half; weights -> transposed half [N][K]
    f2h_kernel<<<(NTOK*DM/4 + 255)/256, 256>>>(x, xh, NTOK*DM/4);
    {
        dim3 bt(32, 8);
        transpose_h_kernel<<<dim3(DM/32,  DM/32),  bt>>>(Wq, wqh, DM,  DM);
        transpose_h_kernel<<<dim3(DM/32,  DM/32),  bt>>>(Wk, wkh, DM,  DM);
        transpose_h_kernel<<<dim3(DM/32,  DM/32),  bt>>>(Wv, wvh, DM,  DM);
        transpose_h_kernel<<<dim3(DM/32,  DM/32),  bt>>>(Wo, woh, DM,  DM);
        transpose_h_kernel<<<dim3(DFF/32, DM/32),  bt>>>(W1, w1h, DM,  DFF);  // -> [DFF][DM]
        transpose_h_kernel<<<dim3(DM/32,  DFF/32), bt>>>(W2, w2h, DFF, DM);   // -> [DM][DFF]
    }

    ln_kernel<<<NTOK, 256>>>(x, ln1_g, ln1_b, xnh);

    dim3 g1(DM / 128, NTOK / 128);     // (8, 32)
    hgemm<false,false,true><<<g1, 128, HGEMM_SMEM>>>(xnh, wqh, bq, nullptr, qh, NTOK, DM, DM);
    hgemm<false,false,true><<<g1, 128, HGEMM_SMEM>>>(xh,  wkh, bk, nullptr, kh, NTOK, DM, DM);
    hgemm<false,false,true><<<g1, 128, HGEMM_SMEM>>>(xh,  wvh, bv, nullptr, vh, NTOK, DM, DM);

    const int pairs = NTOK * NH * (HD / 2);
    rope_h_kernel<<<(pairs + 255) / 256, 256>>>(qh, kh);

    dim3 ga(LL / 64, NH, BB);
    attn_kernel<<<ga, 128>>>(qh, kh, vh, oh);

    hgemm<false,true,false><<<g1, 128, HGEMM_SMEM>>>(oh, woh, bo, x, x2, NTOK, DM, DM);

    ln_kernel<<<NTOK, 256>>>(x2, ln2_g, ln2_b, xn2h);

    dim3 g2(DFF / 128, NTOK / 128);    // (32, 32)
    hgemm<true,false,true><<<g2, 128, HGEMM_SMEM>>>(xn2h, w1h, b1, nullptr, hbh, NTOK, DFF, DM);
    hgemm<false,true,false><<<g1, 128, HGEMM_SMEM>>>(hbh, w2h, b2, x2, out, NTOK, DM, DFF);
}